// round 7
// baseline (speedup 1.0000x reference)
#include <cuda_runtime.h>
#include <math.h>

#define SEQ     2048
#define BATCH   2
#define DIM     1024
#define HEADS   16
#define HD      64
#define HIDDEN  4096
#define TOK     (BATCH * SEQ)   // 4096 tokens

// ---------------- scratch (static device globals; no allocation) ----------------
__device__ float g_h [(size_t)TOK * DIM];
__device__ float g_q [(size_t)TOK * DIM];
__device__ float g_k [(size_t)TOK * DIM];
__device__ float g_v [(size_t)TOK * DIM];
__device__ float g_o [(size_t)TOK * DIM];
__device__ float g_x1[(size_t)TOK * DIM];
__device__ float g_h2[(size_t)TOK * DIM];
__device__ float g_a [(size_t)TOK * HIDDEN];

// ---------------- LayerNorm: one block per row (1024 elems, 256 threads) --------
__global__ __launch_bounds__(256) void ln_kernel(
    const float* __restrict__ x, const float* __restrict__ g,
    const float* __restrict__ b, float* __restrict__ out)
{
    __shared__ float red[8];
    __shared__ float sh_mu, sh_rs;
    const int row = blockIdx.x, tid = threadIdx.x;
    const float* xr = x + (size_t)row * DIM;
    float4 v = *(const float4*)(xr + tid * 4);
    float s = v.x + v.y + v.z + v.w;
    #pragma unroll
    for (int o = 16; o; o >>= 1) s += __shfl_xor_sync(0xffffffffu, s, o);
    if ((tid & 31) == 0) red[tid >> 5] = s;
    __syncthreads();
    if (tid == 0) {
        float t = 0.f;
        #pragma unroll
        for (int i = 0; i < 8; i++) t += red[i];
        sh_mu = t * (1.0f / DIM);
    }
    __syncthreads();
    const float mu = sh_mu;
    float d0 = v.x - mu, d1 = v.y - mu, d2 = v.z - mu, d3 = v.w - mu;
    float s2 = d0*d0 + d1*d1 + d2*d2 + d3*d3;
    #pragma unroll
    for (int o = 16; o; o >>= 1) s2 += __shfl_xor_sync(0xffffffffu, s2, o);
    if ((tid & 31) == 0) red[tid >> 5] = s2;
    __syncthreads();
    if (tid == 0) {
        float t = 0.f;
        #pragma unroll
        for (int i = 0; i < 8; i++) t += red[i];
        sh_rs = rsqrtf(t * (1.0f / DIM) + 1e-5f);
    }
    __syncthreads();
    const float rs = sh_rs;
    float4 gg = *(const float4*)(g + tid * 4);
    float4 bb = *(const float4*)(b + tid * 4);
    float4 o4;
    o4.x = d0 * rs * gg.x + bb.x;
    o4.y = d1 * rs * gg.y + bb.y;
    o4.z = d2 * rs * gg.z + bb.z;
    o4.w = d3 * rs * gg.w + bb.w;
    *(float4*)(out + (size_t)row * DIM + tid * 4) = o4;
}

// ---------------- tiled fp32 GEMM: C[M,N] = A[M,K] @ B[K,N] + bias (+epi) -------
// block 128x128, 256 threads, 8x8 per thread, K-tile 16.
enum { EPI_NONE = 0, EPI_GELU = 1, EPI_RES = 2 };

template<int EPI, bool SCATTER>
__global__ __launch_bounds__(256) void gemm_kernel(
    const float* __restrict__ A, const float* __restrict__ B,
    const float* __restrict__ bias, const float* __restrict__ R,
    float* __restrict__ C, int M, int N, int K)
{
    __shared__ float As[16][132];   // transposed A tile, padded (132 keeps f4 align)
    __shared__ float Bs[16][128];
    const int n0 = blockIdx.x * 128, m0 = blockIdx.y * 128;
    const int tid = threadIdx.x;
    const int tx = tid & 15, ty = tid >> 4;

    float acc[8][8];
    #pragma unroll
    for (int i = 0; i < 8; i++)
        #pragma unroll
        for (int j = 0; j < 8; j++) acc[i][j] = 0.f;

    const int arow = tid >> 2;          // 0..63 (+64 second pass)
    const int aq   = (tid & 3) * 4;
    const int bkr  = tid >> 5;          // 0..7  (+8 second pass)
    const int bcq  = (tid & 31) * 4;

    for (int k0 = 0; k0 < K; k0 += 16) {
        #pragma unroll
        for (int i = 0; i < 2; i++) {
            int row = arow + i * 64;
            float4 va = *(const float4*)(A + (size_t)(m0 + row) * K + k0 + aq);
            As[aq + 0][row] = va.x;
            As[aq + 1][row] = va.y;
            As[aq + 2][row] = va.z;
            As[aq + 3][row] = va.w;
        }
        #pragma unroll
        for (int i = 0; i < 2; i++) {
            int kr = bkr + i * 8;
            *(float4*)(&Bs[kr][bcq]) =
                *(const float4*)(B + (size_t)(k0 + kr) * N + n0 + bcq);
        }
        __syncthreads();
        #pragma unroll
        for (int k = 0; k < 16; k++) {
            float a[8], b[8];
            *(float4*)(a)     = *(const float4*)(&As[k][ty * 8]);
            *(float4*)(a + 4) = *(const float4*)(&As[k][ty * 8 + 4]);
            *(float4*)(b)     = *(const float4*)(&Bs[k][tx * 8]);
            *(float4*)(b + 4) = *(const float4*)(&Bs[k][tx * 8 + 4]);
            #pragma unroll
            for (int i = 0; i < 8; i++)
                #pragma unroll
                for (int j = 0; j < 8; j++)
                    acc[i][j] = fmaf(a[i], b[j], acc[i][j]);
        }
        __syncthreads();
    }

    #pragma unroll
    for (int i = 0; i < 8; i++) {
        const int m = m0 + ty * 8 + i;
        #pragma unroll
        for (int j = 0; j < 8; j++) {
            const int n = n0 + tx * 8 + j;
            float vv = acc[i][j] + bias[n];
            if (EPI == EPI_GELU)
                vv = 0.5f * vv * (1.0f + erff(vv * 0.70710678118654752f));
            if (EPI == EPI_RES)
                vv += R[(size_t)m * N + n];
            if (SCATTER) {  // scatter [tok, C] -> [b, h, t, d] (N==1024 here)
                const int bb = m >> 11, t = m & (SEQ - 1);
                const int hh = n >> 6,  d = n & 63;
                C[(((size_t)(bb * HEADS + hh)) * SEQ + t) * HD + d] = vv;
            } else {
                C[(size_t)m * N + n] = vv;
            }
        }
    }
}

// ---------------- fused attention, online softmax ------------------------------
// grid (32 q-tiles, 32 batch*heads), 256 threads.
// Each block: 64 query rows of one (b,h). Thread (r = tid>>2, c4 = tid&3):
// owns row r; key cols c = 4j+c4 (j<8) per tile; output dims d = 16*i4+4*c4+e.
#define KT 32

__global__ __launch_bounds__(256) void attn_kernel(
    const float* __restrict__ Q, const float* __restrict__ K,
    const float* __restrict__ V, float* __restrict__ O)
{
    __shared__ float Ks[KT][68];
    __shared__ float Vs[KT][68];
    __shared__ float Ps[64][KT + 4];
    const int qt  = blockIdx.x;      // 0..31
    const int bh  = blockIdx.y;      // 0..31  (= b*16 + h)
    const int tid = threadIdx.x;
    const int r   = tid >> 2;        // 0..63
    const int c4  = tid & 3;

    const size_t base = (size_t)bh * SEQ * HD;
    const int qrow = qt * 64 + r;

    // q row in registers, pre-scaled by 1/sqrt(64)
    float qreg[64];
    {
        const float* qp = Q + base + (size_t)qrow * HD;
        #pragma unroll
        for (int k4 = 0; k4 < 16; k4++) {
            float4 t = *(const float4*)(qp + k4 * 4);
            qreg[k4 * 4 + 0] = t.x * 0.125f;
            qreg[k4 * 4 + 1] = t.y * 0.125f;
            qreg[k4 * 4 + 2] = t.z * 0.125f;
            qreg[k4 * 4 + 3] = t.w * 0.125f;
        }
    }

    float m = -INFINITY, l = 0.f;
    float Oacc[16];
    #pragma unroll
    for (int i = 0; i < 16; i++) Oacc[i] = 0.f;

    for (int kt = 0; kt < SEQ / KT; kt++) {
        __syncthreads();   // previous iteration fully consumed Ks/Vs/Ps
        #pragma unroll
        for (int i = 0; i < 2; i++) {
            int idx = tid + i * 256;          // 0..511
            int row = idx >> 4;               // 0..31
            int cq  = (idx & 15) * 4;
            *(float4*)(&Ks[row][cq]) =
                *(const float4*)(K + base + (size_t)(kt * KT + row) * HD + cq);
            *(float4*)(&Vs[row][cq]) =
                *(const float4*)(V + base + (size_t)(kt * KT + row) * HD + cq);
        }
        __syncthreads();

        // ---- S tile: 8 dot products per thread (cols c = 4j + c4) ----
        float s[8];
        #pragma unroll
        for (int j = 0; j < 8; j++) {
            const int c = j * 4 + c4;
            const float* kp = &Ks[c][0];
            float acc = 0.f;
            #pragma unroll
            for (int k4 = 0; k4 < 16; k4++) {
                float4 kv = *(const float4*)(kp + k4 * 4);
                acc = fmaf(qreg[k4 * 4 + 0], kv.x, acc);
                acc = fmaf(qreg[k4 * 4 + 1], kv.y, acc);
                acc = fmaf(qreg[k4 * 4 + 2], kv.z, acc);
                acc = fmaf(qreg[k4 * 4 + 3], kv.w, acc);
            }
            s[j] = acc;
        }

        // ---- online softmax update (row = 4 consecutive lanes) ----
        float tmax = s[0];
        #pragma unroll
        for (int j = 1; j < 8; j++) tmax = fmaxf(tmax, s[j]);
        tmax = fmaxf(tmax, __shfl_xor_sync(0xffffffffu, tmax, 1));
        tmax = fmaxf(tmax, __shfl_xor_sync(0xffffffffu, tmax, 2));
        const float newm = fmaxf(m, tmax);
        const float corr = __expf(m - newm);   // first tile: exp(-inf) = 0
        float psum = 0.f;
        #pragma unroll
        for (int j = 0; j < 8; j++) {
            float p = __expf(s[j] - newm);
            Ps[r][j * 4 + c4] = p;
            psum += p;
        }
        psum += __shfl_xor_sync(0xffffffffu, psum, 1);
        psum += __shfl_xor_sync(0xffffffffu, psum, 2);
        l = l * corr + psum;
        #pragma unroll
        for (int i = 0; i < 16; i++) Oacc[i] *= corr;
        m = newm;
        __syncthreads();   // Ps visible to all lanes of the row

        // ---- O += P @ V (thread dims d = 16*i4 + 4*c4 + e) ----
        #pragma unroll 4
        for (int j = 0; j < KT; j++) {
            const float pv = Ps[r][j];
            #pragma unroll
            for (int i4 = 0; i4 < 4; i4++) {
                float4 vv = *(const float4*)(&Vs[j][i4 * 16 + c4 * 4]);
                Oacc[i4 * 4 + 0] = fmaf(pv, vv.x, Oacc[i4 * 4 + 0]);
                Oacc[i4 * 4 + 1] = fmaf(pv, vv.y, Oacc[i4 * 4 + 1]);
                Oacc[i4 * 4 + 2] = fmaf(pv, vv.z, Oacc[i4 * 4 + 2]);
                Oacc[i4 * 4 + 3] = fmaf(pv, vv.w, Oacc[i4 * 4 + 3]);
            }
        }
    }

    // ---- write O back in [b, t, h*64+d] layout for the O-projection GEMM ----
    const float inv = 1.0f / l;
    const int bb = bh >> 4, hh = bh & 15;
    float* op = O + ((size_t)(bb * SEQ + qrow)) * DIM + hh * HD;
    #pragma unroll
    for (int i4 = 0; i4 < 4; i4++) {
        float4 w;
        w.x = Oacc[i4 * 4 + 0] * inv;
        w.y = Oacc[i4 * 4 + 1] * inv;
        w.z = Oacc[i4 * 4 + 2] * inv;
        w.w = Oacc[i4 * 4 + 3] * inv;
        *(float4*)(op + i4 * 16 + c4 * 4) = w;
    }
}

// ---------------- launch --------------------------------------------------------
extern "C" void kernel_launch(void* const* d_in, const int* in_sizes, int n_in,
                              void* d_out, int out_size)
{
    const float* x   = (const float*)d_in[0];
    const float* g1  = (const float*)d_in[1];
    const float* b1  = (const float*)d_in[2];
    const float* Wq  = (const float*)d_in[3];
    const float* bq  = (const float*)d_in[4];
    const float* Wk  = (const float*)d_in[5];
    const float* bk  = (const float*)d_in[6];
    const float* Wv  = (const float*)d_in[7];
    const float* bv  = (const float*)d_in[8];
    const float* Wo  = (const float*)d_in[9];
    const float* bo  = (const float*)d_in[10];
    const float* g2  = (const float*)d_in[11];
    const float* b2  = (const float*)d_in[12];
    const float* W1  = (const float*)d_in[13];
    const float* bf1 = (const float*)d_in[14];
    const float* W2  = (const float*)d_in[15];
    const float* bf2 = (const float*)d_in[16];
    float* out = (float*)d_out;

    float *h, *q, *k, *v, *o, *x1, *h2, *a;
    cudaGetSymbolAddress((void**)&h,  g_h);
    cudaGetSymbolAddress((void**)&q,  g_q);
    cudaGetSymbolAddress((void**)&k,  g_k);
    cudaGetSymbolAddress((void**)&v,  g_v);
    cudaGetSymbolAddress((void**)&o,  g_o);
    cudaGetSymbolAddress((void**)&x1, g_x1);
    cudaGetSymbolAddress((void**)&h2, g_h2);
    cudaGetSymbolAddress((void**)&a,  g_a);

    // h = LN1(x)
    ln_kernel<<<TOK, 256>>>(x, g1, b1, h);
    // q,k,v = h@W + b, scattered to [b,h,t,d]
    gemm_kernel<EPI_NONE, true ><<<dim3(DIM/128, TOK/128), 256>>>(h, Wq, bq, nullptr, q, TOK, DIM, DIM);
    gemm_kernel<EPI_NONE, true ><<<dim3(DIM/128, TOK/128), 256>>>(h, Wk, bk, nullptr, k, TOK, DIM, DIM);
    gemm_kernel<EPI_NONE, true ><<<dim3(DIM/128, TOK/128), 256>>>(h, Wv, bv, nullptr, v, TOK, DIM, DIM);
    // o = softmax(qk^T/sqrt(d)) v, written as [b,t,C]
    attn_kernel<<<dim3(SEQ/64, BATCH*HEADS), 256>>>(q, k, v, o);
    // x1 = x + o@Wo + bo
    gemm_kernel<EPI_RES,  false><<<dim3(DIM/128, TOK/128), 256>>>(o, Wo, bo, x, x1, TOK, DIM, DIM);
    // h2 = LN2(x1)
    ln_kernel<<<TOK, 256>>>(x1, g2, b2, h2);
    // a = gelu(h2@W1 + bf1)
    gemm_kernel<EPI_GELU, false><<<dim3(HIDDEN/128, TOK/128), 256>>>(h2, W1, bf1, nullptr, a, TOK, HIDDEN, DIM);
    // out = x1 + a@W2 + bf2
    gemm_kernel<EPI_RES,  false><<<dim3(DIM/128, TOK/128), 256>>>(a, W2, bf2, x1, out, TOK, DIM, HIDDEN);
}

// round 9
// speedup vs baseline: 1.0014x; 1.0014x over previous
#include <cuda_runtime.h>
#include <math.h>

#define SEQ     2048
#define BATCH   2
#define DIM     1024
#define HEADS   16
#define HD      64
#define HIDDEN  4096
#define TOK     (BATCH * SEQ)   // 4096 tokens

// ---------------- scratch (static device globals; no allocation) ----------------
__device__ float g_h [(size_t)TOK * DIM];
__device__ float g_q [(size_t)TOK * DIM];
__device__ float g_k [(size_t)TOK * DIM];
__device__ float g_v [(size_t)TOK * DIM];
__device__ float g_o [(size_t)TOK * DIM];
__device__ float g_x1[(size_t)TOK * DIM];
__device__ float g_h2[(size_t)TOK * DIM];
__device__ float g_a [(size_t)TOK * HIDDEN];

// ---------------- LayerNorm: one block per row (1024 elems, 256 threads) --------
__global__ __launch_bounds__(256) void ln_kernel(
    const float* __restrict__ x, const float* __restrict__ g,
    const float* __restrict__ b, float* __restrict__ out)
{
    __shared__ float red[8];
    __shared__ float sh_mu, sh_rs;
    const int row = blockIdx.x, tid = threadIdx.x;
    const float* xr = x + (size_t)row * DIM;
    float4 v = *(const float4*)(xr + tid * 4);
    float s = v.x + v.y + v.z + v.w;
    #pragma unroll
    for (int o = 16; o; o >>= 1) s += __shfl_xor_sync(0xffffffffu, s, o);
    if ((tid & 31) == 0) red[tid >> 5] = s;
    __syncthreads();
    if (tid == 0) {
        float t = 0.f;
        #pragma unroll
        for (int i = 0; i < 8; i++) t += red[i];
        sh_mu = t * (1.0f / DIM);
    }
    __syncthreads();
    const float mu = sh_mu;
    float d0 = v.x - mu, d1 = v.y - mu, d2 = v.z - mu, d3 = v.w - mu;
    float s2 = d0*d0 + d1*d1 + d2*d2 + d3*d3;
    #pragma unroll
    for (int o = 16; o; o >>= 1) s2 += __shfl_xor_sync(0xffffffffu, s2, o);
    if ((tid & 31) == 0) red[tid >> 5] = s2;
    __syncthreads();
    if (tid == 0) {
        float t = 0.f;
        #pragma unroll
        for (int i = 0; i < 8; i++) t += red[i];
        sh_rs = rsqrtf(t * (1.0f / DIM) + 1e-5f);
    }
    __syncthreads();
    const float rs = sh_rs;
    float4 gg = *(const float4*)(g + tid * 4);
    float4 bb = *(const float4*)(b + tid * 4);
    float4 o4;
    o4.x = d0 * rs * gg.x + bb.x;
    o4.y = d1 * rs * gg.y + bb.y;
    o4.z = d2 * rs * gg.z + bb.z;
    o4.w = d3 * rs * gg.w + bb.w;
    *(float4*)(out + (size_t)row * DIM + tid * 4) = o4;
}

// ---------------- tiled fp32 GEMM: C[M,N] = A[M,K] @ B[K,N] + bias (+epi) -------
// block 128x128, 256 threads, 8x8 per thread, K-tile 16.
enum { EPI_NONE = 0, EPI_GELU = 1, EPI_RES = 2 };

template<int EPI, bool SCATTER>
__global__ __launch_bounds__(256) void gemm_kernel(
    const float* __restrict__ A, const float* __restrict__ B,
    const float* __restrict__ bias, const float* __restrict__ R,
    float* __restrict__ C, int M, int N, int K)
{
    __shared__ float As[16][132];   // transposed A tile, padded (132 keeps f4 align)
    __shared__ float Bs[16][128];
    const int n0 = blockIdx.x * 128, m0 = blockIdx.y * 128;
    const int tid = threadIdx.x;
    const int tx = tid & 15, ty = tid >> 4;

    float acc[8][8];
    #pragma unroll
    for (int i = 0; i < 8; i++)
        #pragma unroll
        for (int j = 0; j < 8; j++) acc[i][j] = 0.f;

    const int arow = tid >> 2;          // 0..63 (+64 second pass)
    const int aq   = (tid & 3) * 4;
    const int bkr  = tid >> 5;          // 0..7  (+8 second pass)
    const int bcq  = (tid & 31) * 4;

    for (int k0 = 0; k0 < K; k0 += 16) {
        #pragma unroll
        for (int i = 0; i < 2; i++) {
            int row = arow + i * 64;
            float4 va = *(const float4*)(A + (size_t)(m0 + row) * K + k0 + aq);
            As[aq + 0][row] = va.x;
            As[aq + 1][row] = va.y;
            As[aq + 2][row] = va.z;
            As[aq + 3][row] = va.w;
        }
        #pragma unroll
        for (int i = 0; i < 2; i++) {
            int kr = bkr + i * 8;
            *(float4*)(&Bs[kr][bcq]) =
                *(const float4*)(B + (size_t)(k0 + kr) * N + n0 + bcq);
        }
        __syncthreads();
        #pragma unroll
        for (int k = 0; k < 16; k++) {
            float a[8], b[8];
            *(float4*)(a)     = *(const float4*)(&As[k][ty * 8]);
            *(float4*)(a + 4) = *(const float4*)(&As[k][ty * 8 + 4]);
            *(float4*)(b)     = *(const float4*)(&Bs[k][tx * 8]);
            *(float4*)(b + 4) = *(const float4*)(&Bs[k][tx * 8 + 4]);
            #pragma unroll
            for (int i = 0; i < 8; i++)
                #pragma unroll
                for (int j = 0; j < 8; j++)
                    acc[i][j] = fmaf(a[i], b[j], acc[i][j]);
        }
        __syncthreads();
    }

    #pragma unroll
    for (int i = 0; i < 8; i++) {
        const int m = m0 + ty * 8 + i;
        #pragma unroll
        for (int j = 0; j < 8; j++) {
            const int n = n0 + tx * 8 + j;
            float vv = acc[i][j] + bias[n];
            if (EPI == EPI_GELU)
                vv = 0.5f * vv * (1.0f + erff(vv * 0.70710678118654752f));
            if (EPI == EPI_RES)
                vv += R[(size_t)m * N + n];
            if (SCATTER) {  // scatter [tok, C] -> [b, h, t, d] (N==1024 here)
                const int bb = m >> 11, t = m & (SEQ - 1);
                const int hh = n >> 6,  d = n & 63;
                C[(((size_t)(bb * HEADS + hh)) * SEQ + t) * HD + d] = vv;
            } else {
                C[(size_t)m * N + n] = vv;
            }
        }
    }
}

// ---------------- fused attention, online softmax ------------------------------
// grid (32 q-tiles, 32 batch*heads), 256 threads.
// Each block: 64 query rows of one (b,h). Thread (r = tid>>2, c4 = tid&3):
// owns row r; key cols c = 4j+c4 (j<8) per tile; output dims d = 16*i4+4*c4+e.
#define KT 32

__global__ __launch_bounds__(256) void attn_kernel(
    const float* __restrict__ Q, const float* __restrict__ K,
    const float* __restrict__ V, float* __restrict__ O)
{
    __shared__ float Ks[KT][68];
    __shared__ float Vs[KT][68];
    __shared__ float Ps[64][KT + 4];
    const int qt  = blockIdx.x;      // 0..31
    const int bh  = blockIdx.y;      // 0..31  (= b*16 + h)
    const int tid = threadIdx.x;
    const int r   = tid >> 2;        // 0..63
    const int c4  = tid & 3;

    const size_t base = (size_t)bh * SEQ * HD;
    const int qrow = qt * 64 + r;

    // q row in registers, pre-scaled by 1/sqrt(64)
    float qreg[64];
    {
        const float* qp = Q + base + (size_t)qrow * HD;
        #pragma unroll
        for (int k4 = 0; k4 < 16; k4++) {
            float4 t = *(const float4*)(qp + k4 * 4);
            qreg[k4 * 4 + 0] = t.x * 0.125f;
            qreg[k4 * 4 + 1] = t.y * 0.125f;
            qreg[k4 * 4 + 2] = t.z * 0.125f;
            qreg[k4 * 4 + 3] = t.w * 0.125f;
        }
    }

    float m = -INFINITY, l = 0.f;
    float Oacc[16];
    #pragma unroll
    for (int i = 0; i < 16; i++) Oacc[i] = 0.f;

    for (int kt = 0; kt < SEQ / KT; kt++) {
        __syncthreads();   // previous iteration fully consumed Ks/Vs/Ps
        #pragma unroll
        for (int i = 0; i < 2; i++) {
            int idx = tid + i * 256;          // 0..511
            int row = idx >> 4;               // 0..31
            int cq  = (idx & 15) * 4;
            *(float4*)(&Ks[row][cq]) =
                *(const float4*)(K + base + (size_t)(kt * KT + row) * HD + cq);
            *(float4*)(&Vs[row][cq]) =
                *(const float4*)(V + base + (size_t)(kt * KT + row) * HD + cq);
        }
        __syncthreads();

        // ---- S tile: 8 dot products per thread (cols c = 4j + c4) ----
        float s[8];
        #pragma unroll
        for (int j = 0; j < 8; j++) {
            const int c = j * 4 + c4;
            const float* kp = &Ks[c][0];
            float acc = 0.f;
            #pragma unroll
            for (int k4 = 0; k4 < 16; k4++) {
                float4 kv = *(const float4*)(kp + k4 * 4);
                acc = fmaf(qreg[k4 * 4 + 0], kv.x, acc);
                acc = fmaf(qreg[k4 * 4 + 1], kv.y, acc);
                acc = fmaf(qreg[k4 * 4 + 2], kv.z, acc);
                acc = fmaf(qreg[k4 * 4 + 3], kv.w, acc);
            }
            s[j] = acc;
        }

        // ---- online softmax update (row = 4 consecutive lanes) ----
        float tmax = s[0];
        #pragma unroll
        for (int j = 1; j < 8; j++) tmax = fmaxf(tmax, s[j]);
        tmax = fmaxf(tmax, __shfl_xor_sync(0xffffffffu, tmax, 1));
        tmax = fmaxf(tmax, __shfl_xor_sync(0xffffffffu, tmax, 2));
        const float newm = fmaxf(m, tmax);
        const float corr = __expf(m - newm);   // first tile: exp(-inf) = 0
        float psum = 0.f;
        #pragma unroll
        for (int j = 0; j < 8; j++) {
            float p = __expf(s[j] - newm);
            Ps[r][j * 4 + c4] = p;
            psum += p;
        }
        psum += __shfl_xor_sync(0xffffffffu, psum, 1);
        psum += __shfl_xor_sync(0xffffffffu, psum, 2);
        l = l * corr + psum;
        #pragma unroll
        for (int i = 0; i < 16; i++) Oacc[i] *= corr;
        m = newm;
        __syncthreads();   // Ps visible to all lanes of the row

        // ---- O += P @ V (thread dims d = 16*i4 + 4*c4 + e) ----
        #pragma unroll 4
        for (int j = 0; j < KT; j++) {
            const float pv = Ps[r][j];
            #pragma unroll
            for (int i4 = 0; i4 < 4; i4++) {
                float4 vv = *(const float4*)(&Vs[j][i4 * 16 + c4 * 4]);
                Oacc[i4 * 4 + 0] = fmaf(pv, vv.x, Oacc[i4 * 4 + 0]);
                Oacc[i4 * 4 + 1] = fmaf(pv, vv.y, Oacc[i4 * 4 + 1]);
                Oacc[i4 * 4 + 2] = fmaf(pv, vv.z, Oacc[i4 * 4 + 2]);
                Oacc[i4 * 4 + 3] = fmaf(pv, vv.w, Oacc[i4 * 4 + 3]);
            }
        }
    }

    // ---- write O back in [b, t, h*64+d] layout for the O-projection GEMM ----
    const float inv = 1.0f / l;
    const int bb = bh >> 4, hh = bh & 15;
    float* op = O + ((size_t)(bb * SEQ + qrow)) * DIM + hh * HD;
    #pragma unroll
    for (int i4 = 0; i4 < 4; i4++) {
        float4 w;
        w.x = Oacc[i4 * 4 + 0] * inv;
        w.y = Oacc[i4 * 4 + 1] * inv;
        w.z = Oacc[i4 * 4 + 2] * inv;
        w.w = Oacc[i4 * 4 + 3] * inv;
        *(float4*)(op + i4 * 16 + c4 * 4) = w;
    }
}

// ---------------- launch --------------------------------------------------------
extern "C" void kernel_launch(void* const* d_in, const int* in_sizes, int n_in,
                              void* d_out, int out_size)
{
    const float* x   = (const float*)d_in[0];
    const float* g1  = (const float*)d_in[1];
    const float* b1  = (const float*)d_in[2];
    const float* Wq  = (const float*)d_in[3];
    const float* bq  = (const float*)d_in[4];
    const float* Wk  = (const float*)d_in[5];
    const float* bk  = (const float*)d_in[6];
    const float* Wv  = (const float*)d_in[7];
    const float* bv  = (const float*)d_in[8];
    const float* Wo  = (const float*)d_in[9];
    const float* bo  = (const float*)d_in[10];
    const float* g2  = (const float*)d_in[11];
    const float* b2  = (const float*)d_in[12];
    const float* W1  = (const float*)d_in[13];
    const float* bf1 = (const float*)d_in[14];
    const float* W2  = (const float*)d_in[15];
    const float* bf2 = (const float*)d_in[16];
    float* out = (float*)d_out;

    float *h, *q, *k, *v, *o, *x1, *h2, *a;
    cudaGetSymbolAddress((void**)&h,  g_h);
    cudaGetSymbolAddress((void**)&q,  g_q);
    cudaGetSymbolAddress((void**)&k,  g_k);
    cudaGetSymbolAddress((void**)&v,  g_v);
    cudaGetSymbolAddress((void**)&o,  g_o);
    cudaGetSymbolAddress((void**)&x1, g_x1);
    cudaGetSymbolAddress((void**)&h2, g_h2);
    cudaGetSymbolAddress((void**)&a,  g_a);

    // h = LN1(x)
    ln_kernel<<<TOK, 256>>>(x, g1, b1, h);
    // q,k,v = h@W + b, scattered to [b,h,t,d]
    gemm_kernel<EPI_NONE, true ><<<dim3(DIM/128, TOK/128), 256>>>(h, Wq, bq, nullptr, q, TOK, DIM, DIM);
    gemm_kernel<EPI_NONE, true ><<<dim3(DIM/128, TOK/128), 256>>>(h, Wk, bk, nullptr, k, TOK, DIM, DIM);
    gemm_kernel<EPI_NONE, true ><<<dim3(DIM/128, TOK/128), 256>>>(h, Wv, bv, nullptr, v, TOK, DIM, DIM);
    // o = softmax(qk^T/sqrt(d)) v, written as [b,t,C]
    attn_kernel<<<dim3(SEQ/64, BATCH*HEADS), 256>>>(q, k, v, o);
    // x1 = x + o@Wo + bo
    gemm_kernel<EPI_RES,  false><<<dim3(DIM/128, TOK/128), 256>>>(o, Wo, bo, x, x1, TOK, DIM, DIM);
    // h2 = LN2(x1)
    ln_kernel<<<TOK, 256>>>(x1, g2, b2, h2);
    // a = gelu(h2@W1 + bf1)
    gemm_kernel<EPI_GELU, false><<<dim3(HIDDEN/128, TOK/128), 256>>>(h2, W1, bf1, nullptr, a, TOK, HIDDEN, DIM);
    // out = x1 + a@W2 + bf2
    gemm_kernel<EPI_RES,  false><<<dim3(DIM/128, TOK/128), 256>>>(a, W2, bf2, x1, out, TOK, DIM, HIDDEN);
}

// round 11
// speedup vs baseline: 1.4360x; 1.4340x over previous
#include <cuda_runtime.h>
#include <cuda_bf16.h>
#include <math.h>
#include <stdint.h>

#define SEQ     2048
#define BATCH   2
#define DIM     1024
#define HEADS   16
#define HD      64
#define HIDDEN  4096
#define TOK     (BATCH * SEQ)   // 4096 tokens

typedef __nv_bfloat16 bf16;

// ---------------- scratch (static device globals; no allocation) ----------------
__device__ bf16  g_h_hi [(size_t)TOK * DIM],    g_h_lo [(size_t)TOK * DIM];
__device__ float g_q [(size_t)TOK * DIM];
__device__ float g_k [(size_t)TOK * DIM];
__device__ float g_v [(size_t)TOK * DIM];
__device__ bf16  g_o_hi [(size_t)TOK * DIM],    g_o_lo [(size_t)TOK * DIM];
__device__ float g_x1[(size_t)TOK * DIM];
__device__ bf16  g_h2_hi[(size_t)TOK * DIM],    g_h2_lo[(size_t)TOK * DIM];
__device__ bf16  g_a_hi [(size_t)TOK * HIDDEN], g_a_lo [(size_t)TOK * HIDDEN];

// transposed + bf16-split weights: Wt[n][k] = W[k][n]
__device__ bf16 g_wq_hi[(size_t)DIM * DIM],    g_wq_lo[(size_t)DIM * DIM];
__device__ bf16 g_wk_hi[(size_t)DIM * DIM],    g_wk_lo[(size_t)DIM * DIM];
__device__ bf16 g_wv_hi[(size_t)DIM * DIM],    g_wv_lo[(size_t)DIM * DIM];
__device__ bf16 g_wo_hi[(size_t)DIM * DIM],    g_wo_lo[(size_t)DIM * DIM];
__device__ bf16 g_w1_hi[(size_t)DIM * HIDDEN], g_w1_lo[(size_t)DIM * HIDDEN];
__device__ bf16 g_w2_hi[(size_t)HIDDEN * DIM], g_w2_lo[(size_t)HIDDEN * DIM];

// ---------------- helpers --------------------------------------------------------
static __device__ __forceinline__ uint32_t smem_u32(const void* p) {
    uint32_t a;
    asm("{ .reg .u64 t; cvta.to.shared.u64 t, %1; cvt.u32.u64 %0, t; }" : "=r"(a) : "l"(p));
    return a;
}
static __device__ __forceinline__ uint32_t pk2(bf16 a, bf16 b) {
    __nv_bfloat162 t = __halves2bfloat162(a, b);
    return *reinterpret_cast<uint32_t*>(&t);
}
static __device__ __forceinline__ void split2(float v, bf16& h, bf16& l) {
    h = __float2bfloat16_rn(v);
    l = __float2bfloat16_rn(v - __bfloat162float(h));
}

#define CP16(dst, src) \
    asm volatile("cp.async.cg.shared.global [%0], [%1], 16;" :: "r"(dst), "l"(src) : "memory")
#define CP_COMMIT() asm volatile("cp.async.commit_group;" ::: "memory")
#define CP_WAIT1()  asm volatile("cp.async.wait_group 1;" ::: "memory")
#define CP_WAIT0()  asm volatile("cp.async.wait_group 0;" ::: "memory")

#define LDSM4(r, adr) \
    asm volatile("ldmatrix.sync.aligned.m8n8.x4.shared.b16 {%0,%1,%2,%3}, [%4];" \
        : "=r"((r)[0]), "=r"((r)[1]), "=r"((r)[2]), "=r"((r)[3]) : "r"(adr))

#define MMA(d, a, b) \
    asm volatile("mma.sync.aligned.m16n8k16.row.col.f32.bf16.bf16.f32 " \
        "{%0,%1,%2,%3}, {%4,%5,%6,%7}, {%8,%9}, {%0,%1,%2,%3};" \
        : "+f"((d)[0]), "+f"((d)[1]), "+f"((d)[2]), "+f"((d)[3]) \
        : "r"((a)[0]), "r"((a)[1]), "r"((a)[2]), "r"((a)[3]), "r"((b)[0]), "r"((b)[1]))

// ---------------- weight transpose + bf16 split ---------------------------------
// W [K][N] fp32 -> Hi/Lo [N][K] bf16
__global__ __launch_bounds__(256) void wsplit_kernel(
    const float* __restrict__ W, bf16* __restrict__ Hi,
    bf16* __restrict__ Lo, int K, int N)
{
    __shared__ float t[32][33];
    const int n0 = blockIdx.x * 32, k0 = blockIdx.y * 32;
    const int x = threadIdx.x & 31, y = threadIdx.x >> 5;
    #pragma unroll
    for (int i = 0; i < 4; i++)
        t[y + 8 * i][x] = W[(size_t)(k0 + y + 8 * i) * N + n0 + x];
    __syncthreads();
    #pragma unroll
    for (int i = 0; i < 4; i++) {
        float v = t[x][y + 8 * i];
        bf16 h, l; split2(v, h, l);
        size_t o = (size_t)(n0 + y + 8 * i) * K + k0 + x;
        Hi[o] = h;
        Lo[o] = l;
    }
}

// ---------------- LayerNorm -> bf16 hi/lo ----------------------------------------
__global__ __launch_bounds__(256) void ln_kernel(
    const float* __restrict__ x, const float* __restrict__ g,
    const float* __restrict__ b, bf16* __restrict__ ohi, bf16* __restrict__ olo)
{
    __shared__ float red[8];
    __shared__ float sh_mu, sh_rs;
    const int row = blockIdx.x, tid = threadIdx.x;
    const float* xr = x + (size_t)row * DIM;
    float4 v = *(const float4*)(xr + tid * 4);
    float s = v.x + v.y + v.z + v.w;
    #pragma unroll
    for (int o = 16; o; o >>= 1) s += __shfl_xor_sync(0xffffffffu, s, o);
    if ((tid & 31) == 0) red[tid >> 5] = s;
    __syncthreads();
    if (tid == 0) {
        float t = 0.f;
        #pragma unroll
        for (int i = 0; i < 8; i++) t += red[i];
        sh_mu = t * (1.0f / DIM);
    }
    __syncthreads();
    const float mu = sh_mu;
    float d0 = v.x - mu, d1 = v.y - mu, d2 = v.z - mu, d3 = v.w - mu;
    float s2 = d0*d0 + d1*d1 + d2*d2 + d3*d3;
    #pragma unroll
    for (int o = 16; o; o >>= 1) s2 += __shfl_xor_sync(0xffffffffu, s2, o);
    if ((tid & 31) == 0) red[tid >> 5] = s2;
    __syncthreads();
    if (tid == 0) {
        float t = 0.f;
        #pragma unroll
        for (int i = 0; i < 8; i++) t += red[i];
        sh_rs = rsqrtf(t * (1.0f / DIM) + 1e-5f);
    }
    __syncthreads();
    const float rs = sh_rs;
    float4 gg = *(const float4*)(g + tid * 4);
    float4 bb = *(const float4*)(b + tid * 4);
    float o0 = d0 * rs * gg.x + bb.x;
    float o1 = d1 * rs * gg.y + bb.y;
    float o2 = d2 * rs * gg.z + bb.z;
    float o3 = d3 * rs * gg.w + bb.w;
    bf16 h0,h1,h2,h3,l0,l1,l2,l3;
    split2(o0,h0,l0); split2(o1,h1,l1); split2(o2,h2,l2); split2(o3,h3,l3);
    uint2 hp = make_uint2(pk2(h0,h1), pk2(h2,h3));
    uint2 lp = make_uint2(pk2(l0,l1), pk2(l2,l3));
    *(uint2*)(ohi + (size_t)row * DIM + tid * 4) = hp;
    *(uint2*)(olo + (size_t)row * DIM + tid * 4) = lp;
}

// ---------------- HMMA GEMM: C[M,N] = A @ Wt^T + bias (+epi) --------------------
// A = (Ahi,Alo) bf16 [M][K] row-major; B = (Bhi,Blo) bf16 [N][K] K-major.
// 3 passes: Ahi*Bhi + Ahi*Blo + Alo*Bhi, fp32 accum in registers.
enum { EPI_NONE = 0, EPI_GELU = 1, EPI_RES = 2 };

#define BM 128
#define BN 128
#define BK 32
#define ROWB 80                 // padded smem row stride in bytes (32 bf16 + 8 pad)
#define OFF_AH 0
#define OFF_AL 10240
#define OFF_BH 20480
#define OFF_BL 30720
#define STAGE  40960
#define SM_GEMM (2 * STAGE)     // 81920 bytes

template<int EPI, bool SCATTER, bool OSPLIT>
__global__ __launch_bounds__(256, 1) void gemm_mma(
    const bf16* __restrict__ Ahi, const bf16* __restrict__ Alo,
    const bf16* __restrict__ Bhi, const bf16* __restrict__ Blo,
    const float* __restrict__ bias, const float* __restrict__ R,
    float* __restrict__ C, bf16* __restrict__ Chi, bf16* __restrict__ Clo,
    int M, int N, int K)
{
    extern __shared__ char sm[];
    const uint32_t sb = smem_u32(sm);
    const int tid = threadIdx.x, wid = tid >> 5, lane = tid & 31;
    const int m0 = blockIdx.y * BM, n0 = blockIdx.x * BN;
    const int wm = (wid & 1) * 64, wn = (wid >> 1) * 32;

    // ldmatrix lane addressing
    const int aRow = (lane & 7) + ((lane >> 3) & 1) * 8;
    const int aK   = (lane >> 4) * 16;
    const int bRow = (lane & 7) + (lane >> 4) * 8;
    const int bK   = ((lane >> 3) & 1) * 16;

    float acc[4][4][4];
    #pragma unroll
    for (int i = 0; i < 4; i++)
        #pragma unroll
        for (int j = 0; j < 4; j++)
            #pragma unroll
            for (int q = 0; q < 4; q++) acc[i][j][q] = 0.f;

    const int T = K / BK;

    // stage loader (cp.async, 8 x 16B per thread)
    auto load_stage = [&](int stg, int k0) {
        const uint32_t base = sb + stg * STAGE;
        #pragma unroll
        for (int i = 0; i < 2; i++) {
            int idx = i * 256 + tid;
            int row = idx >> 2, ch = idx & 3;
            uint32_t d = base + row * ROWB + ch * 16;
            size_t ga = (size_t)(m0 + row) * K + k0 + ch * 8;
            size_t gb = (size_t)(n0 + row) * K + k0 + ch * 8;
            CP16(d + OFF_AH, Ahi + ga);
            CP16(d + OFF_AL, Alo + ga);
            CP16(d + OFF_BH, Bhi + gb);
            CP16(d + OFF_BL, Blo + gb);
        }
        CP_COMMIT();
    };

    load_stage(0, 0);

    for (int kt = 0; kt < T; kt++) {
        if (kt + 1 < T) {
            load_stage((kt + 1) & 1, (kt + 1) * BK);
            CP_WAIT1();
        } else {
            CP_WAIT0();
        }
        __syncthreads();

        const uint32_t s = sb + (kt & 1) * STAGE;
        #pragma unroll
        for (int ks = 0; ks < 2; ks++) {
            uint32_t Ah[4][4], Al[4][4], Bh[2][4], Bl[2][4];
            const uint32_t ao = s + (wm + aRow) * ROWB + ks * 32 + aK;
            #pragma unroll
            for (int mt = 0; mt < 4; mt++) {
                LDSM4(Ah[mt], ao + OFF_AH + mt * 16 * ROWB);
                LDSM4(Al[mt], ao + OFF_AL + mt * 16 * ROWB);
            }
            const uint32_t bo = s + (wn + bRow) * ROWB + ks * 32 + bK;
            #pragma unroll
            for (int p = 0; p < 2; p++) {
                LDSM4(Bh[p], bo + OFF_BH + p * 16 * ROWB);
                LDSM4(Bl[p], bo + OFF_BL + p * 16 * ROWB);
            }
            #pragma unroll
            for (int mt = 0; mt < 4; mt++)
                #pragma unroll
                for (int p = 0; p < 2; p++) {
                    MMA(acc[mt][2*p],   Ah[mt], &Bh[p][0]);
                    MMA(acc[mt][2*p+1], Ah[mt], &Bh[p][2]);
                    MMA(acc[mt][2*p],   Ah[mt], &Bl[p][0]);
                    MMA(acc[mt][2*p+1], Ah[mt], &Bl[p][2]);
                    MMA(acc[mt][2*p],   Al[mt], &Bh[p][0]);
                    MMA(acc[mt][2*p+1], Al[mt], &Bh[p][2]);
                }
        }
        __syncthreads();
    }

    // ---- epilogue ----
    const int lr = lane >> 2, lc = (lane & 3) * 2;
    #pragma unroll
    for (int mt = 0; mt < 4; mt++) {
        #pragma unroll
        for (int nt = 0; nt < 4; nt++) {
            #pragma unroll
            for (int hh = 0; hh < 2; hh++) {
                const int m = m0 + wm + mt * 16 + lr + hh * 8;
                const int c = n0 + wn + nt * 8 + lc;
                float v0 = acc[mt][nt][hh * 2 + 0];
                float v1 = acc[mt][nt][hh * 2 + 1];
                float2 b2 = *(const float2*)(bias + c);
                v0 += b2.x; v1 += b2.y;
                if (EPI == EPI_GELU) {
                    v0 = 0.5f * v0 * (1.0f + erff(v0 * 0.70710678118654752f));
                    v1 = 0.5f * v1 * (1.0f + erff(v1 * 0.70710678118654752f));
                }
                if (EPI == EPI_RES) {
                    float2 r2 = *(const float2*)(R + (size_t)m * N + c);
                    v0 += r2.x; v1 += r2.y;
                }
                if (OSPLIT) {
                    bf16 h0, l0, h1, l1;
                    split2(v0, h0, l0); split2(v1, h1, l1);
                    *(uint32_t*)(Chi + (size_t)m * N + c) = pk2(h0, h1);
                    *(uint32_t*)(Clo + (size_t)m * N + c) = pk2(l0, l1);
                } else if (SCATTER) {
                    const int bb = m >> 11, t = m & (SEQ - 1);
                    const int hd = c >> 6, d = c & 63;
                    float* op = C + (((size_t)(bb * HEADS + hd)) * SEQ + t) * HD + d;
                    *(float2*)op = make_float2(v0, v1);
                } else {
                    *(float2*)(C + (size_t)m * N + c) = make_float2(v0, v1);
                }
            }
        }
    }
}

// ---------------- fused attention, online softmax -------------------------------
#define KT 32

__global__ __launch_bounds__(256) void attn_kernel(
    const float* __restrict__ Q, const float* __restrict__ K,
    const float* __restrict__ V, bf16* __restrict__ Ohi, bf16* __restrict__ Olo)
{
    __shared__ float Ks[KT][68];
    __shared__ float Vs[KT][68];
    __shared__ float Ps[64][KT + 4];
    const int qt  = blockIdx.x;
    const int bh  = blockIdx.y;
    const int tid = threadIdx.x;
    const int r   = tid >> 2;
    const int c4  = tid & 3;

    const size_t base = (size_t)bh * SEQ * HD;
    const int qrow = qt * 64 + r;

    float qreg[64];
    {
        const float* qp = Q + base + (size_t)qrow * HD;
        #pragma unroll
        for (int k4 = 0; k4 < 16; k4++) {
            float4 t = *(const float4*)(qp + k4 * 4);
            qreg[k4 * 4 + 0] = t.x * 0.125f;
            qreg[k4 * 4 + 1] = t.y * 0.125f;
            qreg[k4 * 4 + 2] = t.z * 0.125f;
            qreg[k4 * 4 + 3] = t.w * 0.125f;
        }
    }

    float m = -INFINITY, l = 0.f;
    float Oacc[16];
    #pragma unroll
    for (int i = 0; i < 16; i++) Oacc[i] = 0.f;

    for (int kt = 0; kt < SEQ / KT; kt++) {
        __syncthreads();
        #pragma unroll
        for (int i = 0; i < 2; i++) {
            int idx = tid + i * 256;
            int row = idx >> 4;
            int cq  = (idx & 15) * 4;
            *(float4*)(&Ks[row][cq]) =
                *(const float4*)(K + base + (size_t)(kt * KT + row) * HD + cq);
            *(float4*)(&Vs[row][cq]) =
                *(const float4*)(V + base + (size_t)(kt * KT + row) * HD + cq);
        }
        __syncthreads();

        float s[8];
        #pragma unroll
        for (int j = 0; j < 8; j++) {
            const int c = j * 4 + c4;
            const float* kp = &Ks[c][0];
            float acc = 0.f;
            #pragma unroll
            for (int k4 = 0; k4 < 16; k4++) {
                float4 kv = *(const float4*)(kp + k4 * 4);
                acc = fmaf(qreg[k4 * 4 + 0], kv.x, acc);
                acc = fmaf(qreg[k4 * 4 + 1], kv.y, acc);
                acc = fmaf(qreg[k4 * 4 + 2], kv.z, acc);
                acc = fmaf(qreg[k4 * 4 + 3], kv.w, acc);
            }
            s[j] = acc;
        }

        float tmax = s[0];
        #pragma unroll
        for (int j = 1; j < 8; j++) tmax = fmaxf(tmax, s[j]);
        tmax = fmaxf(tmax, __shfl_xor_sync(0xffffffffu, tmax, 1));
        tmax = fmaxf(tmax, __shfl_xor_sync(0xffffffffu, tmax, 2));
        const float newm = fmaxf(m, tmax);
        const float corr = __expf(m - newm);
        float psum = 0.f;
        #pragma unroll
        for (int j = 0; j < 8; j++) {
            float p = __expf(s[j] - newm);
            Ps[r][j * 4 + c4] = p;
            psum += p;
        }
        psum += __shfl_xor_sync(0xffffffffu, psum, 1);
        psum += __shfl_xor_sync(0xffffffffu, psum, 2);
        l = l * corr + psum;
        #pragma unroll
        for (int i = 0; i < 16; i++) Oacc[i] *= corr;
        m = newm;
        __syncthreads();

        #pragma unroll 4
        for (int j = 0; j < KT; j++) {
            const float pv = Ps[r][j];
            #pragma unroll
            for (int i4 = 0; i4 < 4; i4++) {
                float4 vv = *(const float4*)(&Vs[j][i4 * 16 + c4 * 4]);
                Oacc[i4 * 4 + 0] = fmaf(pv, vv.x, Oacc[i4 * 4 + 0]);
                Oacc[i4 * 4 + 1] = fmaf(pv, vv.y, Oacc[i4 * 4 + 1]);
                Oacc[i4 * 4 + 2] = fmaf(pv, vv.z, Oacc[i4 * 4 + 2]);
                Oacc[i4 * 4 + 3] = fmaf(pv, vv.w, Oacc[i4 * 4 + 3]);
            }
        }
    }

    // write O split to bf16 hi/lo in [b, t, h*64+d] layout
    const float inv = 1.0f / l;
    const int bb = bh >> 4, hh = bh & 15;
    const size_t ob = ((size_t)(bb * SEQ + qrow)) * DIM + hh * HD;
    #pragma unroll
    for (int i4 = 0; i4 < 4; i4++) {
        float w0 = Oacc[i4 * 4 + 0] * inv;
        float w1 = Oacc[i4 * 4 + 1] * inv;
        float w2 = Oacc[i4 * 4 + 2] * inv;
        float w3 = Oacc[i4 * 4 + 3] * inv;
        bf16 h0,h1,h2,h3,l0,l1,l2,l3;
        split2(w0,h0,l0); split2(w1,h1,l1); split2(w2,h2,l2); split2(w3,h3,l3);
        *(uint2*)(Ohi + ob + i4 * 16 + c4 * 4) = make_uint2(pk2(h0,h1), pk2(h2,h3));
        *(uint2*)(Olo + ob + i4 * 16 + c4 * 4) = make_uint2(pk2(l0,l1), pk2(l2,l3));
    }
}

// ---------------- launch --------------------------------------------------------
extern "C" void kernel_launch(void* const* d_in, const int* in_sizes, int n_in,
                              void* d_out, int out_size)
{
    const float* x   = (const float*)d_in[0];
    const float* g1  = (const float*)d_in[1];
    const float* b1  = (const float*)d_in[2];
    const float* Wq  = (const float*)d_in[3];
    const float* bq  = (const float*)d_in[4];
    const float* Wk  = (const float*)d_in[5];
    const float* bk  = (const float*)d_in[6];
    const float* Wv  = (const float*)d_in[7];
    const float* bv  = (const float*)d_in[8];
    const float* Wo  = (const float*)d_in[9];
    const float* bo  = (const float*)d_in[10];
    const float* g2  = (const float*)d_in[11];
    const float* b2  = (const float*)d_in[12];
    const float* W1  = (const float*)d_in[13];
    const float* bf1 = (const float*)d_in[14];
    const float* W2  = (const float*)d_in[15];
    const float* bf2 = (const float*)d_in[16];
    float* out = (float*)d_out;

    bf16 *hhi, *hlo, *ohi, *olo, *h2hi, *h2lo, *ahi, *alo;
    float *q, *k, *v, *x1;
    cudaGetSymbolAddress((void**)&hhi,  g_h_hi);  cudaGetSymbolAddress((void**)&hlo,  g_h_lo);
    cudaGetSymbolAddress((void**)&q,    g_q);
    cudaGetSymbolAddress((void**)&k,    g_k);
    cudaGetSymbolAddress((void**)&v,    g_v);
    cudaGetSymbolAddress((void**)&ohi,  g_o_hi);  cudaGetSymbolAddress((void**)&olo,  g_o_lo);
    cudaGetSymbolAddress((void**)&x1,   g_x1);
    cudaGetSymbolAddress((void**)&h2hi, g_h2_hi); cudaGetSymbolAddress((void**)&h2lo, g_h2_lo);
    cudaGetSymbolAddress((void**)&ahi,  g_a_hi);  cudaGetSymbolAddress((void**)&alo,  g_a_lo);

    bf16 *wqh, *wql, *wkh, *wkl, *wvh, *wvl, *woh, *wol, *w1h, *w1l, *w2h, *w2l;
    cudaGetSymbolAddress((void**)&wqh, g_wq_hi); cudaGetSymbolAddress((void**)&wql, g_wq_lo);
    cudaGetSymbolAddress((void**)&wkh, g_wk_hi); cudaGetSymbolAddress((void**)&wkl, g_wk_lo);
    cudaGetSymbolAddress((void**)&wvh, g_wv_hi); cudaGetSymbolAddress((void**)&wvl, g_wv_lo);
    cudaGetSymbolAddress((void**)&woh, g_wo_hi); cudaGetSymbolAddress((void**)&wol, g_wo_lo);
    cudaGetSymbolAddress((void**)&w1h, g_w1_hi); cudaGetSymbolAddress((void**)&w1l, g_w1_lo);
    cudaGetSymbolAddress((void**)&w2h, g_w2_hi); cudaGetSymbolAddress((void**)&w2l, g_w2_lo);

    cudaFuncSetAttribute((const void*)gemm_mma<EPI_NONE, true,  false>,
                         cudaFuncAttributeMaxDynamicSharedMemorySize, SM_GEMM);
    cudaFuncSetAttribute((const void*)gemm_mma<EPI_RES,  false, false>,
                         cudaFuncAttributeMaxDynamicSharedMemorySize, SM_GEMM);
    cudaFuncSetAttribute((const void*)gemm_mma<EPI_GELU, false, true>,
                         cudaFuncAttributeMaxDynamicSharedMemorySize, SM_GEMM);

    // weight transpose + bf16 split
    wsplit_kernel<<<dim3(DIM/32,    DIM/32),    256>>>(Wq, wqh, wql, DIM,    DIM);
    wsplit_kernel<<<dim3(DIM/32,    DIM/32),    256>>>(Wk, wkh, wkl, DIM,    DIM);
    wsplit_kernel<<<dim3(DIM/32,    DIM/32),    256>>>(Wv, wvh, wvl, DIM,    DIM);
    wsplit_kernel<<<dim3(DIM/32,    DIM/32),    256>>>(Wo, woh, wol, DIM,    DIM);
    wsplit_kernel<<<dim3(HIDDEN/32, DIM/32),    256>>>(W1, w1h, w1l, DIM,    HIDDEN);
    wsplit_kernel<<<dim3(DIM/32,    HIDDEN/32), 256>>>(W2, w2h, w2l, HIDDEN, DIM);

    // h = LN1(x), split
    ln_kernel<<<TOK, 256>>>(x, g1, b1, hhi, hlo);
    // q,k,v = h@W + b, scattered to [b,h,t,d] (f32)
    gemm_mma<EPI_NONE, true,  false><<<dim3(DIM/BN, TOK/BM), 256, SM_GEMM>>>(
        hhi, hlo, wqh, wql, bq, nullptr, q, nullptr, nullptr, TOK, DIM, DIM);
    gemm_mma<EPI_NONE, true,  false><<<dim3(DIM/BN, TOK/BM), 256, SM_GEMM>>>(
        hhi, hlo, wkh, wkl, bk, nullptr, k, nullptr, nullptr, TOK, DIM, DIM);
    gemm_mma<EPI_NONE, true,  false><<<dim3(DIM/BN, TOK/BM), 256, SM_GEMM>>>(
        hhi, hlo, wvh, wvl, bv, nullptr, v, nullptr, nullptr, TOK, DIM, DIM);
    // o = softmax(qk^T/sqrt(d)) v, split bf16 [b,t,C]
    attn_kernel<<<dim3(SEQ/64, BATCH*HEADS), 256>>>(q, k, v, ohi, olo);
    // x1 = x + o@Wo + bo  (f32)
    gemm_mma<EPI_RES,  false, false><<<dim3(DIM/BN, TOK/BM), 256, SM_GEMM>>>(
        ohi, olo, woh, wol, bo, x, x1, nullptr, nullptr, TOK, DIM, DIM);
    // h2 = LN2(x1), split
    ln_kernel<<<TOK, 256>>>(x1, g2, b2, h2hi, h2lo);
    // a = gelu(h2@W1 + bf1), split bf16
    gemm_mma<EPI_GELU, false, true ><<<dim3(HIDDEN/BN, TOK/BM), 256, SM_GEMM>>>(
        h2hi, h2lo, w1h, w1l, bf1, nullptr, nullptr, ahi, alo, TOK, HIDDEN, DIM);
    // out = x1 + a@W2 + bf2  (f32)
    gemm_mma<EPI_RES,  false, false><<<dim3(DIM/BN, TOK/BM), 256, SM_GEMM>>>(
        ahi, alo, w2h, w2l, bf2, x1, out, nullptr, nullptr, TOK, DIM, HIDDEN);
}

// round 13
// speedup vs baseline: 3.0403x; 2.1172x over previous
#include <cuda_runtime.h>
#include <cuda_bf16.h>
#include <math.h>
#include <stdint.h>

#define SEQ     2048
#define BATCH   2
#define DIM     1024
#define HEADS   16
#define HD      64
#define HIDDEN  4096
#define TOK     (BATCH * SEQ)   // 4096 tokens

typedef __nv_bfloat16 bf16;

// ---------------- scratch (static device globals; no allocation) ----------------
__device__ bf16  g_h_hi [(size_t)TOK * DIM],    g_h_lo [(size_t)TOK * DIM];
__device__ bf16  g_q_hi [(size_t)TOK * DIM],    g_q_lo [(size_t)TOK * DIM];   // [b,h,t,d]
__device__ bf16  g_k_hi [(size_t)TOK * DIM],    g_k_lo [(size_t)TOK * DIM];   // [b,h,t,d]
__device__ bf16  g_vt_hi[(size_t)TOK * DIM],    g_vt_lo[(size_t)TOK * DIM];   // [b,h,d,t]
__device__ bf16  g_o_hi [(size_t)TOK * DIM],    g_o_lo [(size_t)TOK * DIM];
__device__ float g_x1[(size_t)TOK * DIM];
__device__ bf16  g_h2_hi[(size_t)TOK * DIM],    g_h2_lo[(size_t)TOK * DIM];
__device__ bf16  g_a_hi [(size_t)TOK * HIDDEN], g_a_lo [(size_t)TOK * HIDDEN];

// transposed + bf16-split weights: Wt[n][k] = W[k][n]
__device__ bf16 g_wq_hi[(size_t)DIM * DIM],    g_wq_lo[(size_t)DIM * DIM];
__device__ bf16 g_wk_hi[(size_t)DIM * DIM],    g_wk_lo[(size_t)DIM * DIM];
__device__ bf16 g_wv_hi[(size_t)DIM * DIM],    g_wv_lo[(size_t)DIM * DIM];
__device__ bf16 g_wo_hi[(size_t)DIM * DIM],    g_wo_lo[(size_t)DIM * DIM];
__device__ bf16 g_w1_hi[(size_t)DIM * HIDDEN], g_w1_lo[(size_t)DIM * HIDDEN];
__device__ bf16 g_w2_hi[(size_t)HIDDEN * DIM], g_w2_lo[(size_t)HIDDEN * DIM];

// ---------------- helpers --------------------------------------------------------
static __device__ __forceinline__ uint32_t smem_u32(const void* p) {
    uint32_t a;
    asm("{ .reg .u64 t; cvta.to.shared.u64 t, %1; cvt.u32.u64 %0, t; }" : "=r"(a) : "l"(p));
    return a;
}
static __device__ __forceinline__ uint32_t pk2(bf16 a, bf16 b) {
    __nv_bfloat162 t = __halves2bfloat162(a, b);
    return *reinterpret_cast<uint32_t*>(&t);
}
static __device__ __forceinline__ void split2(float v, bf16& h, bf16& l) {
    h = __float2bfloat16_rn(v);
    l = __float2bfloat16_rn(v - __bfloat162float(h));
}

#define CP16(dst, src) \
    asm volatile("cp.async.cg.shared.global [%0], [%1], 16;" :: "r"(dst), "l"(src) : "memory")
#define CP_COMMIT() asm volatile("cp.async.commit_group;" ::: "memory")
#define CP_WAIT1()  asm volatile("cp.async.wait_group 1;" ::: "memory")
#define CP_WAIT0()  asm volatile("cp.async.wait_group 0;" ::: "memory")

#define LDSM4(r, adr) \
    asm volatile("ldmatrix.sync.aligned.m8n8.x4.shared.b16 {%0,%1,%2,%3}, [%4];" \
        : "=r"((r)[0]), "=r"((r)[1]), "=r"((r)[2]), "=r"((r)[3]) : "r"(adr))

#define MMA(d, a, b) \
    asm volatile("mma.sync.aligned.m16n8k16.row.col.f32.bf16.bf16.f32 " \
        "{%0,%1,%2,%3}, {%4,%5,%6,%7}, {%8,%9}, {%0,%1,%2,%3};" \
        : "+f"((d)[0]), "+f"((d)[1]), "+f"((d)[2]), "+f"((d)[3]) \
        : "r"((a)[0]), "r"((a)[1]), "r"((a)[2]), "r"((a)[3]), "r"((b)[0]), "r"((b)[1]))

// ---------------- weight transpose + bf16 split ---------------------------------
__global__ __launch_bounds__(256) void wsplit_kernel(
    const float* __restrict__ W, bf16* __restrict__ Hi,
    bf16* __restrict__ Lo, int K, int N)
{
    __shared__ float t[32][33];
    const int n0 = blockIdx.x * 32, k0 = blockIdx.y * 32;
    const int x = threadIdx.x & 31, y = threadIdx.x >> 5;
    #pragma unroll
    for (int i = 0; i < 4; i++)
        t[y + 8 * i][x] = W[(size_t)(k0 + y + 8 * i) * N + n0 + x];
    __syncthreads();
    #pragma unroll
    for (int i = 0; i < 4; i++) {
        float v = t[x][y + 8 * i];
        bf16 h, l; split2(v, h, l);
        size_t o = (size_t)(n0 + y + 8 * i) * K + k0 + x;
        Hi[o] = h;
        Lo[o] = l;
    }
}

// ---------------- LayerNorm -> bf16 hi/lo ----------------------------------------
__global__ __launch_bounds__(256) void ln_kernel(
    const float* __restrict__ x, const float* __restrict__ g,
    const float* __restrict__ b, bf16* __restrict__ ohi, bf16* __restrict__ olo)
{
    __shared__ float red[8];
    __shared__ float sh_mu, sh_rs;
    const int row = blockIdx.x, tid = threadIdx.x;
    const float* xr = x + (size_t)row * DIM;
    float4 v = *(const float4*)(xr + tid * 4);
    float s = v.x + v.y + v.z + v.w;
    #pragma unroll
    for (int o = 16; o; o >>= 1) s += __shfl_xor_sync(0xffffffffu, s, o);
    if ((tid & 31) == 0) red[tid >> 5] = s;
    __syncthreads();
    if (tid == 0) {
        float t = 0.f;
        #pragma unroll
        for (int i = 0; i < 8; i++) t += red[i];
        sh_mu = t * (1.0f / DIM);
    }
    __syncthreads();
    const float mu = sh_mu;
    float d0 = v.x - mu, d1 = v.y - mu, d2 = v.z - mu, d3 = v.w - mu;
    float s2 = d0*d0 + d1*d1 + d2*d2 + d3*d3;
    #pragma unroll
    for (int o = 16; o; o >>= 1) s2 += __shfl_xor_sync(0xffffffffu, s2, o);
    if ((tid & 31) == 0) red[tid >> 5] = s2;
    __syncthreads();
    if (tid == 0) {
        float t = 0.f;
        #pragma unroll
        for (int i = 0; i < 8; i++) t += red[i];
        sh_rs = rsqrtf(t * (1.0f / DIM) + 1e-5f);
    }
    __syncthreads();
    const float rs = sh_rs;
    float4 gg = *(const float4*)(g + tid * 4);
    float4 bb = *(const float4*)(b + tid * 4);
    float o0 = d0 * rs * gg.x + bb.x;
    float o1 = d1 * rs * gg.y + bb.y;
    float o2 = d2 * rs * gg.z + bb.z;
    float o3 = d3 * rs * gg.w + bb.w;
    bf16 h0,h1,h2,h3,l0,l1,l2,l3;
    split2(o0,h0,l0); split2(o1,h1,l1); split2(o2,h2,l2); split2(o3,h3,l3);
    *(uint2*)(ohi + (size_t)row * DIM + tid * 4) = make_uint2(pk2(h0,h1), pk2(h2,h3));
    *(uint2*)(olo + (size_t)row * DIM + tid * 4) = make_uint2(pk2(l0,l1), pk2(l2,l3));
}

// ---------------- HMMA GEMM: C[M,N] = A @ Wt^T + bias (+epi) --------------------
// 3 passes: Ahi*Bhi + Ahi*Blo + Alo*Bhi, fp32 accum in registers.
// SCMODE: 0 = plain/row-major, 1 = scatter bf16 hi/lo [b,h,t,d], 2 = scatter [b,h,d,t]
enum { EPI_NONE = 0, EPI_GELU = 1, EPI_RES = 2 };

#define BM 128
#define BN 128
#define BK 32
#define ROWB 80
#define OFF_AH 0
#define OFF_AL 10240
#define OFF_BH 20480
#define OFF_BL 30720
#define STAGE  40960
#define SM_GEMM (2 * STAGE)

template<int EPI, int SCMODE, bool OSPLIT>
__global__ __launch_bounds__(256, 1) void gemm_mma(
    const bf16* __restrict__ Ahi, const bf16* __restrict__ Alo,
    const bf16* __restrict__ Bhi, const bf16* __restrict__ Blo,
    const float* __restrict__ bias, const float* __restrict__ R,
    float* __restrict__ C, bf16* __restrict__ Chi, bf16* __restrict__ Clo,
    int M, int N, int K)
{
    extern __shared__ char sm[];
    const uint32_t sb = smem_u32(sm);
    const int tid = threadIdx.x, wid = tid >> 5, lane = tid & 31;
    const int m0 = blockIdx.y * BM, n0 = blockIdx.x * BN;
    const int wm = (wid & 1) * 64, wn = (wid >> 1) * 32;

    const int aRow = (lane & 7) + ((lane >> 3) & 1) * 8;
    const int aK   = (lane >> 4) * 16;
    const int bRow = (lane & 7) + (lane >> 4) * 8;
    const int bK   = ((lane >> 3) & 1) * 16;

    float acc[4][4][4];
    #pragma unroll
    for (int i = 0; i < 4; i++)
        #pragma unroll
        for (int j = 0; j < 4; j++)
            #pragma unroll
            for (int q = 0; q < 4; q++) acc[i][j][q] = 0.f;

    const int T = K / BK;

    auto load_stage = [&](int stg, int k0) {
        const uint32_t base = sb + stg * STAGE;
        #pragma unroll
        for (int i = 0; i < 2; i++) {
            int idx = i * 256 + tid;
            int row = idx >> 2, ch = idx & 3;
            uint32_t d = base + row * ROWB + ch * 16;
            size_t ga = (size_t)(m0 + row) * K + k0 + ch * 8;
            size_t gb = (size_t)(n0 + row) * K + k0 + ch * 8;
            CP16(d + OFF_AH, Ahi + ga);
            CP16(d + OFF_AL, Alo + ga);
            CP16(d + OFF_BH, Bhi + gb);
            CP16(d + OFF_BL, Blo + gb);
        }
        CP_COMMIT();
    };

    load_stage(0, 0);

    for (int kt = 0; kt < T; kt++) {
        if (kt + 1 < T) {
            load_stage((kt + 1) & 1, (kt + 1) * BK);
            CP_WAIT1();
        } else {
            CP_WAIT0();
        }
        __syncthreads();

        const uint32_t s = sb + (kt & 1) * STAGE;
        #pragma unroll
        for (int ks = 0; ks < 2; ks++) {
            uint32_t Ah[4][4], Al[4][4], Bh[2][4], Bl[2][4];
            const uint32_t ao = s + (wm + aRow) * ROWB + ks * 32 + aK;
            #pragma unroll
            for (int mt = 0; mt < 4; mt++) {
                LDSM4(Ah[mt], ao + OFF_AH + mt * 16 * ROWB);
                LDSM4(Al[mt], ao + OFF_AL + mt * 16 * ROWB);
            }
            const uint32_t bo = s + (wn + bRow) * ROWB + ks * 32 + bK;
            #pragma unroll
            for (int p = 0; p < 2; p++) {
                LDSM4(Bh[p], bo + OFF_BH + p * 16 * ROWB);
                LDSM4(Bl[p], bo + OFF_BL + p * 16 * ROWB);
            }
            #pragma unroll
            for (int mt = 0; mt < 4; mt++)
                #pragma unroll
                for (int p = 0; p < 2; p++) {
                    MMA(acc[mt][2*p],   Ah[mt], &Bh[p][0]);
                    MMA(acc[mt][2*p+1], Ah[mt], &Bh[p][2]);
                    MMA(acc[mt][2*p],   Ah[mt], &Bl[p][0]);
                    MMA(acc[mt][2*p+1], Ah[mt], &Bl[p][2]);
                    MMA(acc[mt][2*p],   Al[mt], &Bh[p][0]);
                    MMA(acc[mt][2*p+1], Al[mt], &Bh[p][2]);
                }
        }
        __syncthreads();
    }

    const int lr = lane >> 2, lc = (lane & 3) * 2;
    #pragma unroll
    for (int mt = 0; mt < 4; mt++) {
        #pragma unroll
        for (int nt = 0; nt < 4; nt++) {
            #pragma unroll
            for (int hh = 0; hh < 2; hh++) {
                const int m = m0 + wm + mt * 16 + lr + hh * 8;
                const int c = n0 + wn + nt * 8 + lc;
                float v0 = acc[mt][nt][hh * 2 + 0];
                float v1 = acc[mt][nt][hh * 2 + 1];
                float2 b2 = *(const float2*)(bias + c);
                v0 += b2.x; v1 += b2.y;
                if (EPI == EPI_GELU) {
                    v0 = 0.5f * v0 * (1.0f + erff(v0 * 0.70710678118654752f));
                    v1 = 0.5f * v1 * (1.0f + erff(v1 * 0.70710678118654752f));
                }
                if (EPI == EPI_RES) {
                    float2 r2 = *(const float2*)(R + (size_t)m * N + c);
                    v0 += r2.x; v1 += r2.y;
                }
                if (OSPLIT) {
                    bf16 h0, l0, h1, l1;
                    split2(v0, h0, l0); split2(v1, h1, l1);
                    *(uint32_t*)(Chi + (size_t)m * N + c) = pk2(h0, h1);
                    *(uint32_t*)(Clo + (size_t)m * N + c) = pk2(l0, l1);
                } else if (SCMODE == 1) {       // Q/K: bf16 hi/lo [b,h,t,d]
                    const int bb = m >> 11, t = m & (SEQ - 1);
                    const int hd = c >> 6, d = c & 63;
                    size_t o = (((size_t)(bb * HEADS + hd)) * SEQ + t) * HD + d;
                    bf16 h0, l0, h1, l1;
                    split2(v0, h0, l0); split2(v1, h1, l1);
                    *(uint32_t*)(Chi + o) = pk2(h0, h1);
                    *(uint32_t*)(Clo + o) = pk2(l0, l1);
                } else if (SCMODE == 2) {       // V: bf16 hi/lo transposed [b,h,d,t]
                    const int bb = m >> 11, t = m & (SEQ - 1);
                    const int hd = c >> 6, d = c & 63;
                    size_t o0 = (((size_t)(bb * HEADS + hd)) * HD + d) * SEQ + t;
                    bf16 h0, l0, h1, l1;
                    split2(v0, h0, l0); split2(v1, h1, l1);
                    Chi[o0] = h0;       Clo[o0] = l0;
                    Chi[o0 + SEQ] = h1; Clo[o0 + SEQ] = l1;
                } else {
                    *(float2*)(C + (size_t)m * N + c) = make_float2(v0, v1);
                }
            }
        }
    }
}

// ---------------- flash attention with mma.sync ---------------------------------
// block: 128 q rows of one (b,h); 8 warps x 16 rows; key tile 64, double-buffered.
// S = 3-pass hi/lo bf16, softmax fp32 in regs, P@V = 3-pass hi/lo.
#define QROW 144                         // 64 bf16 = 128B + 16 pad
#define A_OFFQH 0
#define A_OFFQL 18432
#define A_STG0  36864
#define A_STGSZ 36864                    // KH 9216 | KL 9216 | VH 9216 | VL 9216
#define SM_ATTN (A_STG0 + 2 * A_STGSZ)   // 110592

__global__ __launch_bounds__(256, 1) void attn_mma(
    const bf16* __restrict__ Qhi, const bf16* __restrict__ Qlo,
    const bf16* __restrict__ Khi, const bf16* __restrict__ Klo,
    const bf16* __restrict__ Vhi, const bf16* __restrict__ Vlo,
    bf16* __restrict__ Ohi, bf16* __restrict__ Olo)
{
    extern __shared__ char sm[];
    const uint32_t sb = smem_u32(sm);
    const int tid = threadIdx.x, wid = tid >> 5, lane = tid & 31;
    const int qt = blockIdx.x;           // 0..15
    const int bh = blockIdx.y;           // 0..31
    const size_t base = (size_t)bh * SEQ * HD;   // same base for K[b,h,t,d] and Vt[b,h,d,t]
    const size_t qbase = base + (size_t)(qt * 128) * HD;

    // ---- load Q tile 128x64 hi/lo to smem ----
    #pragma unroll
    for (int i = 0; i < 4; i++) {
        int idx = i * 256 + tid;
        int row = idx >> 3, ch = idx & 7;
        *(uint4*)(sm + A_OFFQH + row * QROW + ch * 16) =
            *(const uint4*)(Qhi + qbase + row * HD + ch * 8);
        *(uint4*)(sm + A_OFFQL + row * QROW + ch * 16) =
            *(const uint4*)(Qlo + qbase + row * HD + ch * 8);
    }
    __syncthreads();

    const int aRow = (lane & 7) + ((lane >> 3) & 1) * 8;
    const int aK   = (lane >> 4) * 16;
    const int bRow = (lane & 7) + (lane >> 4) * 8;
    const int bK   = ((lane >> 3) & 1) * 16;

    // ---- Q fragments (persistent) ----
    uint32_t QH[4][4], QL[4][4];
    {
        const uint32_t qa = sb + (wid * 16 + aRow) * QROW + aK;
        #pragma unroll
        for (int ks = 0; ks < 4; ks++) {
            LDSM4(QH[ks], qa + A_OFFQH + ks * 32);
            LDSM4(QL[ks], qa + A_OFFQL + ks * 32);
        }
    }

    // ---- KV stage loader ----
    auto load_kv = [&](int stg, int kt0) {
        const uint32_t bse = sb + A_STG0 + stg * A_STGSZ;
        #pragma unroll
        for (int i = 0; i < 2; i++) {
            int idx = i * 256 + tid;
            int row = idx >> 3, ch = idx & 7;          // row 0..63, ch 0..7
            uint32_t d = bse + row * QROW + ch * 16;
            size_t gk = base + (size_t)(kt0 + row) * HD + ch * 8;   // K row = key
            size_t gv = base + (size_t)row * SEQ + kt0 + ch * 8;    // Vt row = dim
            CP16(d,         Khi + gk);
            CP16(d + 9216,  Klo + gk);
            CP16(d + 18432, Vhi + gv);
            CP16(d + 27648, Vlo + gv);
        }
        CP_COMMIT();
    };

    float Oa[8][4];
    #pragma unroll
    for (int j = 0; j < 8; j++)
        #pragma unroll
        for (int q = 0; q < 4; q++) Oa[j][q] = 0.f;
    float m0 = -INFINITY, m1 = -INFINITY, l0 = 0.f, l1 = 0.f;

    load_kv(0, 0);

    const int NT = SEQ / 64;   // 32
    for (int kt = 0; kt < NT; kt++) {
        if (kt + 1 < NT) {
            load_kv((kt + 1) & 1, (kt + 1) * 64);
            CP_WAIT1();
        } else {
            CP_WAIT0();
        }
        __syncthreads();

        const uint32_t s = sb + A_STG0 + (kt & 1) * A_STGSZ;

        // ---- S = Q K^T (3-pass) ----
        float S[8][4];
        #pragma unroll
        for (int j = 0; j < 8; j++)
            #pragma unroll
            for (int q = 0; q < 4; q++) S[j][q] = 0.f;

        #pragma unroll
        for (int ks = 0; ks < 4; ks++) {
            uint32_t KH[4][4], KL[4][4];
            const uint32_t ka = s + bRow * QROW + ks * 32 + bK;
            #pragma unroll
            for (int p = 0; p < 4; p++) {
                LDSM4(KH[p], ka + p * 16 * QROW);
                LDSM4(KL[p], ka + 9216 + p * 16 * QROW);
            }
            #pragma unroll
            for (int p = 0; p < 4; p++) {
                MMA(S[2*p],   QH[ks], &KH[p][0]);
                MMA(S[2*p+1], QH[ks], &KH[p][2]);
                MMA(S[2*p],   QH[ks], &KL[p][0]);
                MMA(S[2*p+1], QH[ks], &KL[p][2]);
                MMA(S[2*p],   QL[ks], &KH[p][0]);
                MMA(S[2*p+1], QL[ks], &KH[p][2]);
            }
        }

        // ---- online softmax (rows lr = lane>>2 and lr+8) ----
        #pragma unroll
        for (int j = 0; j < 8; j++) {
            S[j][0] *= 0.125f; S[j][1] *= 0.125f;
            S[j][2] *= 0.125f; S[j][3] *= 0.125f;
        }
        float r0 = S[0][0], r1 = S[0][2];
        #pragma unroll
        for (int j = 0; j < 8; j++) {
            r0 = fmaxf(r0, fmaxf(S[j][0], S[j][1]));
            r1 = fmaxf(r1, fmaxf(S[j][2], S[j][3]));
        }
        r0 = fmaxf(r0, __shfl_xor_sync(0xffffffffu, r0, 1));
        r0 = fmaxf(r0, __shfl_xor_sync(0xffffffffu, r0, 2));
        r1 = fmaxf(r1, __shfl_xor_sync(0xffffffffu, r1, 1));
        r1 = fmaxf(r1, __shfl_xor_sync(0xffffffffu, r1, 2));
        const float nm0 = fmaxf(m0, r0), nm1 = fmaxf(m1, r1);
        const float c0 = __expf(m0 - nm0), c1 = __expf(m1 - nm1);
        m0 = nm0; m1 = nm1;
        float s0 = 0.f, s1 = 0.f;
        #pragma unroll
        for (int j = 0; j < 8; j++) {
            S[j][0] = __expf(S[j][0] - m0); s0 += S[j][0];
            S[j][1] = __expf(S[j][1] - m0); s0 += S[j][1];
            S[j][2] = __expf(S[j][2] - m1); s1 += S[j][2];
            S[j][3] = __expf(S[j][3] - m1); s1 += S[j][3];
        }
        s0 += __shfl_xor_sync(0xffffffffu, s0, 1);
        s0 += __shfl_xor_sync(0xffffffffu, s0, 2);
        s1 += __shfl_xor_sync(0xffffffffu, s1, 1);
        s1 += __shfl_xor_sync(0xffffffffu, s1, 2);
        l0 = l0 * c0 + s0;
        l1 = l1 * c1 + s1;
        #pragma unroll
        for (int j = 0; j < 8; j++) {
            Oa[j][0] *= c0; Oa[j][1] *= c0;
            Oa[j][2] *= c1; Oa[j][3] *= c1;
        }

        // ---- O += P V (3-pass); P frags built from S accum (FA2 identity) ----
        #pragma unroll
        for (int kk = 0; kk < 4; kk++) {
            uint32_t PH[4], PL[4];
            #pragma unroll
            for (int hf = 0; hf < 2; hf++) {     // hf=0: cols lo half, hf=1: +8
                const int j = 2 * kk + hf;
                bf16 h0,l0b,h1,l1b,h2,l2b,h3,l3b;
                split2(S[j][0], h0, l0b); split2(S[j][1], h1, l1b);
                split2(S[j][2], h2, l2b); split2(S[j][3], h3, l3b);
                PH[hf * 2 + 0] = pk2(h0, h1);  PL[hf * 2 + 0] = pk2(l0b, l1b);
                PH[hf * 2 + 1] = pk2(h2, h3);  PL[hf * 2 + 1] = pk2(l2b, l3b);
            }
            uint32_t VH[4][4], VL[4][4];
            const uint32_t va = s + 18432 + bRow * QROW + kk * 32 + bK;
            #pragma unroll
            for (int p = 0; p < 4; p++) {
                LDSM4(VH[p], va + p * 16 * QROW);
                LDSM4(VL[p], va + 9216 + p * 16 * QROW);
            }
            #pragma unroll
            for (int p = 0; p < 4; p++) {
                MMA(Oa[2*p],   PH, &VH[p][0]);
                MMA(Oa[2*p+1], PH, &VH[p][2]);
                MMA(Oa[2*p],   PH, &VL[p][0]);
                MMA(Oa[2*p+1], PH, &VL[p][2]);
                MMA(Oa[2*p],   PL, &VH[p][0]);
                MMA(Oa[2*p+1], PL, &VH[p][2]);
            }
        }
        __syncthreads();
    }

    // ---- write O (bf16 hi/lo, [b, t, h*64+d]) ----
    const float i0 = 1.0f / l0, i1 = 1.0f / l1;
    const int bb = bh >> 4, hh = bh & 15;
    const int r0w = qt * 128 + wid * 16 + (lane >> 2);
    const size_t t0 = ((size_t)(bb * SEQ + r0w)) * DIM + hh * HD;
    const size_t t1 = t0 + (size_t)8 * DIM;
    #pragma unroll
    for (int j = 0; j < 8; j++) {
        const int d = j * 8 + (lane & 3) * 2;
        float v0 = Oa[j][0] * i0, v1 = Oa[j][1] * i0;
        float v2 = Oa[j][2] * i1, v3 = Oa[j][3] * i1;
        bf16 h0,lo0,h1,lo1,h2,lo2,h3,lo3;
        split2(v0,h0,lo0); split2(v1,h1,lo1);
        split2(v2,h2,lo2); split2(v3,h3,lo3);
        *(uint32_t*)(Ohi + t0 + d) = pk2(h0, h1);
        *(uint32_t*)(Olo + t0 + d) = pk2(lo0, lo1);
        *(uint32_t*)(Ohi + t1 + d) = pk2(h2, h3);
        *(uint32_t*)(Olo + t1 + d) = pk2(lo2, lo3);
    }
}

// ---------------- launch --------------------------------------------------------
extern "C" void kernel_launch(void* const* d_in, const int* in_sizes, int n_in,
                              void* d_out, int out_size)
{
    const float* x   = (const float*)d_in[0];
    const float* g1  = (const float*)d_in[1];
    const float* b1  = (const float*)d_in[2];
    const float* Wq  = (const float*)d_in[3];
    const float* bq  = (const float*)d_in[4];
    const float* Wk  = (const float*)d_in[5];
    const float* bk  = (const float*)d_in[6];
    const float* Wv  = (const float*)d_in[7];
    const float* bv  = (const float*)d_in[8];
    const float* Wo  = (const float*)d_in[9];
    const float* bo  = (const float*)d_in[10];
    const float* g2  = (const float*)d_in[11];
    const float* b2  = (const float*)d_in[12];
    const float* W1  = (const float*)d_in[13];
    const float* bf1 = (const float*)d_in[14];
    const float* W2  = (const float*)d_in[15];
    const float* bf2 = (const float*)d_in[16];
    float* out = (float*)d_out;

    bf16 *hhi, *hlo, *qhi, *qlo, *khi, *klo, *vthi, *vtlo;
    bf16 *ohi, *olo, *h2hi, *h2lo, *ahi, *alo;
    float *x1;
    cudaGetSymbolAddress((void**)&hhi,  g_h_hi);  cudaGetSymbolAddress((void**)&hlo,  g_h_lo);
    cudaGetSymbolAddress((void**)&qhi,  g_q_hi);  cudaGetSymbolAddress((void**)&qlo,  g_q_lo);
    cudaGetSymbolAddress((void**)&khi,  g_k_hi);  cudaGetSymbolAddress((void**)&klo,  g_k_lo);
    cudaGetSymbolAddress((void**)&vthi, g_vt_hi); cudaGetSymbolAddress((void**)&vtlo, g_vt_lo);
    cudaGetSymbolAddress((void**)&ohi,  g_o_hi);  cudaGetSymbolAddress((void**)&olo,  g_o_lo);
    cudaGetSymbolAddress((void**)&x1,   g_x1);
    cudaGetSymbolAddress((void**)&h2hi, g_h2_hi); cudaGetSymbolAddress((void**)&h2lo, g_h2_lo);
    cudaGetSymbolAddress((void**)&ahi,  g_a_hi);  cudaGetSymbolAddress((void**)&alo,  g_a_lo);

    bf16 *wqh, *wql, *wkh, *wkl, *wvh, *wvl, *woh, *wol, *w1h, *w1l, *w2h, *w2l;
    cudaGetSymbolAddress((void**)&wqh, g_wq_hi); cudaGetSymbolAddress((void**)&wql, g_wq_lo);
    cudaGetSymbolAddress((void**)&wkh, g_wk_hi); cudaGetSymbolAddress((void**)&wkl, g_wk_lo);
    cudaGetSymbolAddress((void**)&wvh, g_wv_hi); cudaGetSymbolAddress((void**)&wvl, g_wv_lo);
    cudaGetSymbolAddress((void**)&woh, g_wo_hi); cudaGetSymbolAddress((void**)&wol, g_wo_lo);
    cudaGetSymbolAddress((void**)&w1h, g_w1_hi); cudaGetSymbolAddress((void**)&w1l, g_w1_lo);
    cudaGetSymbolAddress((void**)&w2h, g_w2_hi); cudaGetSymbolAddress((void**)&w2l, g_w2_lo);

    cudaFuncSetAttribute((const void*)gemm_mma<EPI_NONE, 1, false>,
                         cudaFuncAttributeMaxDynamicSharedMemorySize, SM_GEMM);
    cudaFuncSetAttribute((const void*)gemm_mma<EPI_NONE, 2, false>,
                         cudaFuncAttributeMaxDynamicSharedMemorySize, SM_GEMM);
    cudaFuncSetAttribute((const void*)gemm_mma<EPI_RES,  0, false>,
                         cudaFuncAttributeMaxDynamicSharedMemorySize, SM_GEMM);
    cudaFuncSetAttribute((const void*)gemm_mma<EPI_GELU, 0, true>,
                         cudaFuncAttributeMaxDynamicSharedMemorySize, SM_GEMM);
    cudaFuncSetAttribute((const void*)attn_mma,
                         cudaFuncAttributeMaxDynamicSharedMemorySize, SM_ATTN);

    // weight transpose + bf16 split
    wsplit_kernel<<<dim3(DIM/32,    DIM/32),    256>>>(Wq, wqh, wql, DIM,    DIM);
    wsplit_kernel<<<dim3(DIM/32,    DIM/32),    256>>>(Wk, wkh, wkl, DIM,    DIM);
    wsplit_kernel<<<dim3(DIM/32,    DIM/32),    256>>>(Wv, wvh, wvl, DIM,    DIM);
    wsplit_kernel<<<dim3(DIM/32,    DIM/32),    256>>>(Wo, woh, wol, DIM,    DIM);
    wsplit_kernel<<<dim3(HIDDEN/32, DIM/32),    256>>>(W1, w1h, w1l, DIM,    HIDDEN);
    wsplit_kernel<<<dim3(DIM/32,    HIDDEN/32), 256>>>(W2, w2h, w2l, HIDDEN, DIM);

    // h = LN1(x), split
    ln_kernel<<<TOK, 256>>>(x, g1, b1, hhi, hlo);
    // q,k = h@W + b -> bf16 hi/lo [b,h,t,d]; v -> bf16 hi/lo [b,h,d,t]
    gemm_mma<EPI_NONE, 1, false><<<dim3(DIM/BN, TOK/BM), 256, SM_GEMM>>>(
        hhi, hlo, wqh, wql, bq, nullptr, nullptr, qhi, qlo, TOK, DIM, DIM);
    gemm_mma<EPI_NONE, 1, false><<<dim3(DIM/BN, TOK/BM), 256, SM_GEMM>>>(
        hhi, hlo, wkh, wkl, bk, nullptr, nullptr, khi, klo, TOK, DIM, DIM);
    gemm_mma<EPI_NONE, 2, false><<<dim3(DIM/BN, TOK/BM), 256, SM_GEMM>>>(
        hhi, hlo, wvh, wvl, bv, nullptr, nullptr, vthi, vtlo, TOK, DIM, DIM);
    // o = softmax(qk^T/8) v -> bf16 hi/lo [b,t,C]
    attn_mma<<<dim3(SEQ/128, BATCH*HEADS), 256, SM_ATTN>>>(
        qhi, qlo, khi, klo, vthi, vtlo, ohi, olo);
    // x1 = x + o@Wo + bo  (f32)
    gemm_mma<EPI_RES, 0, false><<<dim3(DIM/BN, TOK/BM), 256, SM_GEMM>>>(
        ohi, olo, woh, wol, bo, x, x1, nullptr, nullptr, TOK, DIM, DIM);
    // h2 = LN2(x1), split
    ln_kernel<<<TOK, 256>>>(x1, g2, b2, h2hi, h2lo);
    // a = gelu(h2@W1 + bf1), split bf16
    gemm_mma<EPI_GELU, 0, true ><<<dim3(HIDDEN/BN, TOK/BM), 256, SM_GEMM>>>(
        h2hi, h2lo, w1h, w1l, bf1, nullptr, nullptr, ahi, alo, TOK, HIDDEN, DIM);
    // out = x1 + a@W2 + bf2  (f32)
    gemm_mma<EPI_RES, 0, false><<<dim3(DIM/BN, TOK/BM), 256, SM_GEMM>>>(
        ahi, alo, w2h, w2l, bf2, x1, out, nullptr, nullptr, TOK, DIM, HIDDEN);
}

// round 14
// speedup vs baseline: 3.0413x; 1.0003x over previous
#include <cuda_runtime.h>
#include <cuda_bf16.h>
#include <math.h>
#include <stdint.h>

#define SEQ     2048
#define BATCH   2
#define DIM     1024
#define HEADS   16
#define HD      64
#define HIDDEN  4096
#define TOK     (BATCH * SEQ)   // 4096 tokens

typedef __nv_bfloat16 bf16;

// ---------------- scratch (static device globals; no allocation) ----------------
__device__ bf16  g_h_hi [(size_t)TOK * DIM],    g_h_lo [(size_t)TOK * DIM];
__device__ bf16  g_q_hi [(size_t)TOK * DIM],    g_q_lo [(size_t)TOK * DIM];   // [b,h,t,d]
__device__ bf16  g_k_hi [(size_t)TOK * DIM],    g_k_lo [(size_t)TOK * DIM];   // [b,h,t,d]
__device__ bf16  g_vt_hi[(size_t)TOK * DIM],    g_vt_lo[(size_t)TOK * DIM];   // [b,h,d,t]
__device__ bf16  g_o_hi [(size_t)TOK * DIM],    g_o_lo [(size_t)TOK * DIM];
__device__ float g_x1[(size_t)TOK * DIM];
__device__ bf16  g_h2_hi[(size_t)TOK * DIM],    g_h2_lo[(size_t)TOK * DIM];
__device__ bf16  g_a_hi [(size_t)TOK * HIDDEN], g_a_lo [(size_t)TOK * HIDDEN];

// transposed + bf16-split weights: Wt[n][k] = W[k][n]
__device__ bf16 g_wq_hi[(size_t)DIM * DIM],    g_wq_lo[(size_t)DIM * DIM];
__device__ bf16 g_wk_hi[(size_t)DIM * DIM],    g_wk_lo[(size_t)DIM * DIM];
__device__ bf16 g_wv_hi[(size_t)DIM * DIM],    g_wv_lo[(size_t)DIM * DIM];
__device__ bf16 g_wo_hi[(size_t)DIM * DIM],    g_wo_lo[(size_t)DIM * DIM];
__device__ bf16 g_w1_hi[(size_t)DIM * HIDDEN], g_w1_lo[(size_t)DIM * HIDDEN];
__device__ bf16 g_w2_hi[(size_t)HIDDEN * DIM], g_w2_lo[(size_t)HIDDEN * DIM];

// ---------------- helpers --------------------------------------------------------
static __device__ __forceinline__ uint32_t smem_u32(const void* p) {
    uint32_t a;
    asm("{ .reg .u64 t; cvta.to.shared.u64 t, %1; cvt.u32.u64 %0, t; }" : "=r"(a) : "l"(p));
    return a;
}
static __device__ __forceinline__ uint32_t pk2(bf16 a, bf16 b) {
    __nv_bfloat162 t = __halves2bfloat162(a, b);
    return *reinterpret_cast<uint32_t*>(&t);
}
static __device__ __forceinline__ void split2(float v, bf16& h, bf16& l) {
    h = __float2bfloat16_rn(v);
    l = __float2bfloat16_rn(v - __bfloat162float(h));
}

#define CP16(dst, src) \
    asm volatile("cp.async.cg.shared.global [%0], [%1], 16;" :: "r"(dst), "l"(src) : "memory")
#define CP_COMMIT() asm volatile("cp.async.commit_group;" ::: "memory")
#define CP_WAIT1()  asm volatile("cp.async.wait_group 1;" ::: "memory")
#define CP_WAIT0()  asm volatile("cp.async.wait_group 0;" ::: "memory")

#define LDSM4(r, adr) \
    asm volatile("ldmatrix.sync.aligned.m8n8.x4.shared.b16 {%0,%1,%2,%3}, [%4];" \
        : "=r"((r)[0]), "=r"((r)[1]), "=r"((r)[2]), "=r"((r)[3]) : "r"(adr))

#define MMA(d, a, b) \
    asm volatile("mma.sync.aligned.m16n8k16.row.col.f32.bf16.bf16.f32 " \
        "{%0,%1,%2,%3}, {%4,%5,%6,%7}, {%8,%9}, {%0,%1,%2,%3};" \
        : "+f"((d)[0]), "+f"((d)[1]), "+f"((d)[2]), "+f"((d)[3]) \
        : "r"((a)[0]), "r"((a)[1]), "r"((a)[2]), "r"((a)[3]), "r"((b)[0]), "r"((b)[1]))

// ---------------- weight transpose + bf16 split ---------------------------------
__global__ __launch_bounds__(256) void wsplit_kernel(
    const float* __restrict__ W, bf16* __restrict__ Hi,
    bf16* __restrict__ Lo, int K, int N)
{
    __shared__ float t[32][33];
    const int n0 = blockIdx.x * 32, k0 = blockIdx.y * 32;
    const int x = threadIdx.x & 31, y = threadIdx.x >> 5;
    #pragma unroll
    for (int i = 0; i < 4; i++)
        t[y + 8 * i][x] = W[(size_t)(k0 + y + 8 * i) * N + n0 + x];
    __syncthreads();
    #pragma unroll
    for (int i = 0; i < 4; i++) {
        float v = t[x][y + 8 * i];
        bf16 h, l; split2(v, h, l);
        size_t o = (size_t)(n0 + y + 8 * i) * K + k0 + x;
        Hi[o] = h;
        Lo[o] = l;
    }
}

// ---------------- LayerNorm -> bf16 hi/lo ----------------------------------------
__global__ __launch_bounds__(256) void ln_kernel(
    const float* __restrict__ x, const float* __restrict__ g,
    const float* __restrict__ b, bf16* __restrict__ ohi, bf16* __restrict__ olo)
{
    __shared__ float red[8];
    __shared__ float sh_mu, sh_rs;
    const int row = blockIdx.x, tid = threadIdx.x;
    const float* xr = x + (size_t)row * DIM;
    float4 v = *(const float4*)(xr + tid * 4);
    float s = v.x + v.y + v.z + v.w;
    #pragma unroll
    for (int o = 16; o; o >>= 1) s += __shfl_xor_sync(0xffffffffu, s, o);
    if ((tid & 31) == 0) red[tid >> 5] = s;
    __syncthreads();
    if (tid == 0) {
        float t = 0.f;
        #pragma unroll
        for (int i = 0; i < 8; i++) t += red[i];
        sh_mu = t * (1.0f / DIM);
    }
    __syncthreads();
    const float mu = sh_mu;
    float d0 = v.x - mu, d1 = v.y - mu, d2 = v.z - mu, d3 = v.w - mu;
    float s2 = d0*d0 + d1*d1 + d2*d2 + d3*d3;
    #pragma unroll
    for (int o = 16; o; o >>= 1) s2 += __shfl_xor_sync(0xffffffffu, s2, o);
    if ((tid & 31) == 0) red[tid >> 5] = s2;
    __syncthreads();
    if (tid == 0) {
        float t = 0.f;
        #pragma unroll
        for (int i = 0; i < 8; i++) t += red[i];
        sh_rs = rsqrtf(t * (1.0f / DIM) + 1e-5f);
    }
    __syncthreads();
    const float rs = sh_rs;
    float4 gg = *(const float4*)(g + tid * 4);
    float4 bb = *(const float4*)(b + tid * 4);
    float o0 = d0 * rs * gg.x + bb.x;
    float o1 = d1 * rs * gg.y + bb.y;
    float o2 = d2 * rs * gg.z + bb.z;
    float o3 = d3 * rs * gg.w + bb.w;
    bf16 h0,h1,h2,h3,l0,l1,l2,l3;
    split2(o0,h0,l0); split2(o1,h1,l1); split2(o2,h2,l2); split2(o3,h3,l3);
    *(uint2*)(ohi + (size_t)row * DIM + tid * 4) = make_uint2(pk2(h0,h1), pk2(h2,h3));
    *(uint2*)(olo + (size_t)row * DIM + tid * 4) = make_uint2(pk2(l0,l1), pk2(l2,l3));
}

// ---------------- HMMA GEMM: C[M,N] = A @ Wt^T + bias (+epi) --------------------
// 3 passes: Ahi*Bhi + Ahi*Blo + Alo*Bhi, fp32 accum in registers.
// SCMODE: 0 = plain/row-major, 1 = scatter bf16 hi/lo [b,h,t,d], 2 = scatter [b,h,d,t]
enum { EPI_NONE = 0, EPI_GELU = 1, EPI_RES = 2 };

#define BM 128
#define BN 128
#define BK 32
#define ROWB 80
#define OFF_AH 0
#define OFF_AL 10240
#define OFF_BH 20480
#define OFF_BL 30720
#define STAGE  40960
#define SM_GEMM (2 * STAGE)

template<int EPI, int SCMODE, bool OSPLIT>
__global__ __launch_bounds__(256, 1) void gemm_mma(
    const bf16* __restrict__ Ahi, const bf16* __restrict__ Alo,
    const bf16* __restrict__ Bhi, const bf16* __restrict__ Blo,
    const float* __restrict__ bias, const float* __restrict__ R,
    float* __restrict__ C, bf16* __restrict__ Chi, bf16* __restrict__ Clo,
    int M, int N, int K)
{
    extern __shared__ char sm[];
    const uint32_t sb = smem_u32(sm);
    const int tid = threadIdx.x, wid = tid >> 5, lane = tid & 31;
    const int m0 = blockIdx.y * BM, n0 = blockIdx.x * BN;
    const int wm = (wid & 1) * 64, wn = (wid >> 1) * 32;

    const int aRow = (lane & 7) + ((lane >> 3) & 1) * 8;
    const int aK   = (lane >> 4) * 16;
    const int bRow = (lane & 7) + (lane >> 4) * 8;
    const int bK   = ((lane >> 3) & 1) * 16;

    float acc[4][4][4];
    #pragma unroll
    for (int i = 0; i < 4; i++)
        #pragma unroll
        for (int j = 0; j < 4; j++)
            #pragma unroll
            for (int q = 0; q < 4; q++) acc[i][j][q] = 0.f;

    const int T = K / BK;

    auto load_stage = [&](int stg, int k0) {
        const uint32_t base = sb + stg * STAGE;
        #pragma unroll
        for (int i = 0; i < 2; i++) {
            int idx = i * 256 + tid;
            int row = idx >> 2, ch = idx & 3;
            uint32_t d = base + row * ROWB + ch * 16;
            size_t ga = (size_t)(m0 + row) * K + k0 + ch * 8;
            size_t gb = (size_t)(n0 + row) * K + k0 + ch * 8;
            CP16(d + OFF_AH, Ahi + ga);
            CP16(d + OFF_AL, Alo + ga);
            CP16(d + OFF_BH, Bhi + gb);
            CP16(d + OFF_BL, Blo + gb);
        }
        CP_COMMIT();
    };

    load_stage(0, 0);

    for (int kt = 0; kt < T; kt++) {
        if (kt + 1 < T) {
            load_stage((kt + 1) & 1, (kt + 1) * BK);
            CP_WAIT1();
        } else {
            CP_WAIT0();
        }
        __syncthreads();

        const uint32_t s = sb + (kt & 1) * STAGE;
        #pragma unroll
        for (int ks = 0; ks < 2; ks++) {
            uint32_t Ah[4][4], Al[4][4], Bh[2][4], Bl[2][4];
            const uint32_t ao = s + (wm + aRow) * ROWB + ks * 32 + aK;
            #pragma unroll
            for (int mt = 0; mt < 4; mt++) {
                LDSM4(Ah[mt], ao + OFF_AH + mt * 16 * ROWB);
                LDSM4(Al[mt], ao + OFF_AL + mt * 16 * ROWB);
            }
            const uint32_t bo = s + (wn + bRow) * ROWB + ks * 32 + bK;
            #pragma unroll
            for (int p = 0; p < 2; p++) {
                LDSM4(Bh[p], bo + OFF_BH + p * 16 * ROWB);
                LDSM4(Bl[p], bo + OFF_BL + p * 16 * ROWB);
            }
            #pragma unroll
            for (int mt = 0; mt < 4; mt++)
                #pragma unroll
                for (int p = 0; p < 2; p++) {
                    MMA(acc[mt][2*p],   Ah[mt], &Bh[p][0]);
                    MMA(acc[mt][2*p+1], Ah[mt], &Bh[p][2]);
                    MMA(acc[mt][2*p],   Ah[mt], &Bl[p][0]);
                    MMA(acc[mt][2*p+1], Ah[mt], &Bl[p][2]);
                    MMA(acc[mt][2*p],   Al[mt], &Bh[p][0]);
                    MMA(acc[mt][2*p+1], Al[mt], &Bh[p][2]);
                }
        }
        __syncthreads();
    }

    const int lr = lane >> 2, lc = (lane & 3) * 2;
    #pragma unroll
    for (int mt = 0; mt < 4; mt++) {
        #pragma unroll
        for (int nt = 0; nt < 4; nt++) {
            #pragma unroll
            for (int hh = 0; hh < 2; hh++) {
                const int m = m0 + wm + mt * 16 + lr + hh * 8;
                const int c = n0 + wn + nt * 8 + lc;
                float v0 = acc[mt][nt][hh * 2 + 0];
                float v1 = acc[mt][nt][hh * 2 + 1];
                float2 b2 = *(const float2*)(bias + c);
                v0 += b2.x; v1 += b2.y;
                if (EPI == EPI_GELU) {
                    v0 = 0.5f * v0 * (1.0f + erff(v0 * 0.70710678118654752f));
                    v1 = 0.5f * v1 * (1.0f + erff(v1 * 0.70710678118654752f));
                }
                if (EPI == EPI_RES) {
                    float2 r2 = *(const float2*)(R + (size_t)m * N + c);
                    v0 += r2.x; v1 += r2.y;
                }
                if (OSPLIT) {
                    bf16 h0, l0, h1, l1;
                    split2(v0, h0, l0); split2(v1, h1, l1);
                    *(uint32_t*)(Chi + (size_t)m * N + c) = pk2(h0, h1);
                    *(uint32_t*)(Clo + (size_t)m * N + c) = pk2(l0, l1);
                } else if (SCMODE == 1) {       // Q/K: bf16 hi/lo [b,h,t,d]
                    const int bb = m >> 11, t = m & (SEQ - 1);
                    const int hd = c >> 6, d = c & 63;
                    size_t o = (((size_t)(bb * HEADS + hd)) * SEQ + t) * HD + d;
                    bf16 h0, l0, h1, l1;
                    split2(v0, h0, l0); split2(v1, h1, l1);
                    *(uint32_t*)(Chi + o) = pk2(h0, h1);
                    *(uint32_t*)(Clo + o) = pk2(l0, l1);
                } else if (SCMODE == 2) {       // V: bf16 hi/lo transposed [b,h,d,t]
                    const int bb = m >> 11, t = m & (SEQ - 1);
                    const int hd = c >> 6, d = c & 63;
                    size_t o0 = (((size_t)(bb * HEADS + hd)) * HD + d) * SEQ + t;
                    bf16 h0, l0, h1, l1;
                    split2(v0, h0, l0); split2(v1, h1, l1);
                    Chi[o0] = h0;       Clo[o0] = l0;
                    Chi[o0 + SEQ] = h1; Clo[o0 + SEQ] = l1;
                } else {
                    *(float2*)(C + (size_t)m * N + c) = make_float2(v0, v1);
                }
            }
        }
    }
}

// ---------------- flash attention with mma.sync ---------------------------------
// block: 128 q rows of one (b,h); 8 warps x 16 rows; key tile 64, double-buffered.
// S = 3-pass hi/lo bf16, softmax fp32 in regs, P@V = 3-pass hi/lo.
#define QROW 144                         // 64 bf16 = 128B + 16 pad
#define A_OFFQH 0
#define A_OFFQL 18432
#define A_STG0  36864
#define A_STGSZ 36864                    // KH 9216 | KL 9216 | VH 9216 | VL 9216
#define SM_ATTN (A_STG0 + 2 * A_STGSZ)   // 110592

__global__ __launch_bounds__(256, 1) void attn_mma(
    const bf16* __restrict__ Qhi, const bf16* __restrict__ Qlo,
    const bf16* __restrict__ Khi, const bf16* __restrict__ Klo,
    const bf16* __restrict__ Vhi, const bf16* __restrict__ Vlo,
    bf16* __restrict__ Ohi, bf16* __restrict__ Olo)
{
    extern __shared__ char sm[];
    const uint32_t sb = smem_u32(sm);
    const int tid = threadIdx.x, wid = tid >> 5, lane = tid & 31;
    const int qt = blockIdx.x;           // 0..15
    const int bh = blockIdx.y;           // 0..31
    const size_t base = (size_t)bh * SEQ * HD;   // same base for K[b,h,t,d] and Vt[b,h,d,t]
    const size_t qbase = base + (size_t)(qt * 128) * HD;

    // ---- load Q tile 128x64 hi/lo to smem ----
    #pragma unroll
    for (int i = 0; i < 4; i++) {
        int idx = i * 256 + tid;
        int row = idx >> 3, ch = idx & 7;
        *(uint4*)(sm + A_OFFQH + row * QROW + ch * 16) =
            *(const uint4*)(Qhi + qbase + row * HD + ch * 8);
        *(uint4*)(sm + A_OFFQL + row * QROW + ch * 16) =
            *(const uint4*)(Qlo + qbase + row * HD + ch * 8);
    }
    __syncthreads();

    const int aRow = (lane & 7) + ((lane >> 3) & 1) * 8;
    const int aK   = (lane >> 4) * 16;
    const int bRow = (lane & 7) + (lane >> 4) * 8;
    const int bK   = ((lane >> 3) & 1) * 16;

    // ---- Q fragments (persistent) ----
    uint32_t QH[4][4], QL[4][4];
    {
        const uint32_t qa = sb + (wid * 16 + aRow) * QROW + aK;
        #pragma unroll
        for (int ks = 0; ks < 4; ks++) {
            LDSM4(QH[ks], qa + A_OFFQH + ks * 32);
            LDSM4(QL[ks], qa + A_OFFQL + ks * 32);
        }
    }

    // ---- KV stage loader ----
    auto load_kv = [&](int stg, int kt0) {
        const uint32_t bse = sb + A_STG0 + stg * A_STGSZ;
        #pragma unroll
        for (int i = 0; i < 2; i++) {
            int idx = i * 256 + tid;
            int row = idx >> 3, ch = idx & 7;          // row 0..63, ch 0..7
            uint32_t d = bse + row * QROW + ch * 16;
            size_t gk = base + (size_t)(kt0 + row) * HD + ch * 8;   // K row = key
            size_t gv = base + (size_t)row * SEQ + kt0 + ch * 8;    // Vt row = dim
            CP16(d,         Khi + gk);
            CP16(d + 9216,  Klo + gk);
            CP16(d + 18432, Vhi + gv);
            CP16(d + 27648, Vlo + gv);
        }
        CP_COMMIT();
    };

    float Oa[8][4];
    #pragma unroll
    for (int j = 0; j < 8; j++)
        #pragma unroll
        for (int q = 0; q < 4; q++) Oa[j][q] = 0.f;
    float m0 = -INFINITY, m1 = -INFINITY, l0 = 0.f, l1 = 0.f;

    load_kv(0, 0);

    const int NT = SEQ / 64;   // 32
    for (int kt = 0; kt < NT; kt++) {
        if (kt + 1 < NT) {
            load_kv((kt + 1) & 1, (kt + 1) * 64);
            CP_WAIT1();
        } else {
            CP_WAIT0();
        }
        __syncthreads();

        const uint32_t s = sb + A_STG0 + (kt & 1) * A_STGSZ;

        // ---- S = Q K^T (3-pass) ----
        float S[8][4];
        #pragma unroll
        for (int j = 0; j < 8; j++)
            #pragma unroll
            for (int q = 0; q < 4; q++) S[j][q] = 0.f;

        #pragma unroll
        for (int ks = 0; ks < 4; ks++) {
            uint32_t KH[4][4], KL[4][4];
            const uint32_t ka = s + bRow * QROW + ks * 32 + bK;
            #pragma unroll
            for (int p = 0; p < 4; p++) {
                LDSM4(KH[p], ka + p * 16 * QROW);
                LDSM4(KL[p], ka + 9216 + p * 16 * QROW);
            }
            #pragma unroll
            for (int p = 0; p < 4; p++) {
                MMA(S[2*p],   QH[ks], &KH[p][0]);
                MMA(S[2*p+1], QH[ks], &KH[p][2]);
                MMA(S[2*p],   QH[ks], &KL[p][0]);
                MMA(S[2*p+1], QH[ks], &KL[p][2]);
                MMA(S[2*p],   QL[ks], &KH[p][0]);
                MMA(S[2*p+1], QL[ks], &KH[p][2]);
            }
        }

        // ---- online softmax (rows lr = lane>>2 and lr+8) ----
        #pragma unroll
        for (int j = 0; j < 8; j++) {
            S[j][0] *= 0.125f; S[j][1] *= 0.125f;
            S[j][2] *= 0.125f; S[j][3] *= 0.125f;
        }
        float r0 = S[0][0], r1 = S[0][2];
        #pragma unroll
        for (int j = 0; j < 8; j++) {
            r0 = fmaxf(r0, fmaxf(S[j][0], S[j][1]));
            r1 = fmaxf(r1, fmaxf(S[j][2], S[j][3]));
        }
        r0 = fmaxf(r0, __shfl_xor_sync(0xffffffffu, r0, 1));
        r0 = fmaxf(r0, __shfl_xor_sync(0xffffffffu, r0, 2));
        r1 = fmaxf(r1, __shfl_xor_sync(0xffffffffu, r1, 1));
        r1 = fmaxf(r1, __shfl_xor_sync(0xffffffffu, r1, 2));
        const float nm0 = fmaxf(m0, r0), nm1 = fmaxf(m1, r1);
        const float c0 = __expf(m0 - nm0), c1 = __expf(m1 - nm1);
        m0 = nm0; m1 = nm1;
        float s0 = 0.f, s1 = 0.f;
        #pragma unroll
        for (int j = 0; j < 8; j++) {
            S[j][0] = __expf(S[j][0] - m0); s0 += S[j][0];
            S[j][1] = __expf(S[j][1] - m0); s0 += S[j][1];
            S[j][2] = __expf(S[j][2] - m1); s1 += S[j][2];
            S[j][3] = __expf(S[j][3] - m1); s1 += S[j][3];
        }
        s0 += __shfl_xor_sync(0xffffffffu, s0, 1);
        s0 += __shfl_xor_sync(0xffffffffu, s0, 2);
        s1 += __shfl_xor_sync(0xffffffffu, s1, 1);
        s1 += __shfl_xor_sync(0xffffffffu, s1, 2);
        l0 = l0 * c0 + s0;
        l1 = l1 * c1 + s1;
        #pragma unroll
        for (int j = 0; j < 8; j++) {
            Oa[j][0] *= c0; Oa[j][1] *= c0;
            Oa[j][2] *= c1; Oa[j][3] *= c1;
        }

        // ---- O += P V (3-pass); P frags built from S accum (FA2 identity) ----
        #pragma unroll
        for (int kk = 0; kk < 4; kk++) {
            uint32_t PH[4], PL[4];
            #pragma unroll
            for (int hf = 0; hf < 2; hf++) {     // hf=0: cols lo half, hf=1: +8
                const int j = 2 * kk + hf;
                bf16 h0,l0b,h1,l1b,h2,l2b,h3,l3b;
                split2(S[j][0], h0, l0b); split2(S[j][1], h1, l1b);
                split2(S[j][2], h2, l2b); split2(S[j][3], h3, l3b);
                PH[hf * 2 + 0] = pk2(h0, h1);  PL[hf * 2 + 0] = pk2(l0b, l1b);
                PH[hf * 2 + 1] = pk2(h2, h3);  PL[hf * 2 + 1] = pk2(l2b, l3b);
            }
            uint32_t VH[4][4], VL[4][4];
            const uint32_t va = s + 18432 + bRow * QROW + kk * 32 + bK;
            #pragma unroll
            for (int p = 0; p < 4; p++) {
                LDSM4(VH[p], va + p * 16 * QROW);
                LDSM4(VL[p], va + 9216 + p * 16 * QROW);
            }
            #pragma unroll
            for (int p = 0; p < 4; p++) {
                MMA(Oa[2*p],   PH, &VH[p][0]);
                MMA(Oa[2*p+1], PH, &VH[p][2]);
                MMA(Oa[2*p],   PH, &VL[p][0]);
                MMA(Oa[2*p+1], PH, &VL[p][2]);
                MMA(Oa[2*p],   PL, &VH[p][0]);
                MMA(Oa[2*p+1], PL, &VH[p][2]);
            }
        }
        __syncthreads();
    }

    // ---- write O (bf16 hi/lo, [b, t, h*64+d]) ----
    const float i0 = 1.0f / l0, i1 = 1.0f / l1;
    const int bb = bh >> 4, hh = bh & 15;
    const int r0w = qt * 128 + wid * 16 + (lane >> 2);
    const size_t t0 = ((size_t)(bb * SEQ + r0w)) * DIM + hh * HD;
    const size_t t1 = t0 + (size_t)8 * DIM;
    #pragma unroll
    for (int j = 0; j < 8; j++) {
        const int d = j * 8 + (lane & 3) * 2;
        float v0 = Oa[j][0] * i0, v1 = Oa[j][1] * i0;
        float v2 = Oa[j][2] * i1, v3 = Oa[j][3] * i1;
        bf16 h0,lo0,h1,lo1,h2,lo2,h3,lo3;
        split2(v0,h0,lo0); split2(v1,h1,lo1);
        split2(v2,h2,lo2); split2(v3,h3,lo3);
        *(uint32_t*)(Ohi + t0 + d) = pk2(h0, h1);
        *(uint32_t*)(Olo + t0 + d) = pk2(lo0, lo1);
        *(uint32_t*)(Ohi + t1 + d) = pk2(h2, h3);
        *(uint32_t*)(Olo + t1 + d) = pk2(lo2, lo3);
    }
}

// ---------------- launch --------------------------------------------------------
extern "C" void kernel_launch(void* const* d_in, const int* in_sizes, int n_in,
                              void* d_out, int out_size)
{
    const float* x   = (const float*)d_in[0];
    const float* g1  = (const float*)d_in[1];
    const float* b1  = (const float*)d_in[2];
    const float* Wq  = (const float*)d_in[3];
    const float* bq  = (const float*)d_in[4];
    const float* Wk  = (const float*)d_in[5];
    const float* bk  = (const float*)d_in[6];
    const float* Wv  = (const float*)d_in[7];
    const float* bv  = (const float*)d_in[8];
    const float* Wo  = (const float*)d_in[9];
    const float* bo  = (const float*)d_in[10];
    const float* g2  = (const float*)d_in[11];
    const float* b2  = (const float*)d_in[12];
    const float* W1  = (const float*)d_in[13];
    const float* bf1 = (const float*)d_in[14];
    const float* W2  = (const float*)d_in[15];
    const float* bf2 = (const float*)d_in[16];
    float* out = (float*)d_out;

    bf16 *hhi, *hlo, *qhi, *qlo, *khi, *klo, *vthi, *vtlo;
    bf16 *ohi, *olo, *h2hi, *h2lo, *ahi, *alo;
    float *x1;
    cudaGetSymbolAddress((void**)&hhi,  g_h_hi);  cudaGetSymbolAddress((void**)&hlo,  g_h_lo);
    cudaGetSymbolAddress((void**)&qhi,  g_q_hi);  cudaGetSymbolAddress((void**)&qlo,  g_q_lo);
    cudaGetSymbolAddress((void**)&khi,  g_k_hi);  cudaGetSymbolAddress((void**)&klo,  g_k_lo);
    cudaGetSymbolAddress((void**)&vthi, g_vt_hi); cudaGetSymbolAddress((void**)&vtlo, g_vt_lo);
    cudaGetSymbolAddress((void**)&ohi,  g_o_hi);  cudaGetSymbolAddress((void**)&olo,  g_o_lo);
    cudaGetSymbolAddress((void**)&x1,   g_x1);
    cudaGetSymbolAddress((void**)&h2hi, g_h2_hi); cudaGetSymbolAddress((void**)&h2lo, g_h2_lo);
    cudaGetSymbolAddress((void**)&ahi,  g_a_hi);  cudaGetSymbolAddress((void**)&alo,  g_a_lo);

    bf16 *wqh, *wql, *wkh, *wkl, *wvh, *wvl, *woh, *wol, *w1h, *w1l, *w2h, *w2l;
    cudaGetSymbolAddress((void**)&wqh, g_wq_hi); cudaGetSymbolAddress((void**)&wql, g_wq_lo);
    cudaGetSymbolAddress((void**)&wkh, g_wk_hi); cudaGetSymbolAddress((void**)&wkl, g_wk_lo);
    cudaGetSymbolAddress((void**)&wvh, g_wv_hi); cudaGetSymbolAddress((void**)&wvl, g_wv_lo);
    cudaGetSymbolAddress((void**)&woh, g_wo_hi); cudaGetSymbolAddress((void**)&wol, g_wo_lo);
    cudaGetSymbolAddress((void**)&w1h, g_w1_hi); cudaGetSymbolAddress((void**)&w1l, g_w1_lo);
    cudaGetSymbolAddress((void**)&w2h, g_w2_hi); cudaGetSymbolAddress((void**)&w2l, g_w2_lo);

    cudaFuncSetAttribute((const void*)gemm_mma<EPI_NONE, 1, false>,
                         cudaFuncAttributeMaxDynamicSharedMemorySize, SM_GEMM);
    cudaFuncSetAttribute((const void*)gemm_mma<EPI_NONE, 2, false>,
                         cudaFuncAttributeMaxDynamicSharedMemorySize, SM_GEMM);
    cudaFuncSetAttribute((const void*)gemm_mma<EPI_RES,  0, false>,
                         cudaFuncAttributeMaxDynamicSharedMemorySize, SM_GEMM);
    cudaFuncSetAttribute((const void*)gemm_mma<EPI_GELU, 0, true>,
                         cudaFuncAttributeMaxDynamicSharedMemorySize, SM_GEMM);
    cudaFuncSetAttribute((const void*)attn_mma,
                         cudaFuncAttributeMaxDynamicSharedMemorySize, SM_ATTN);

    // weight transpose + bf16 split
    wsplit_kernel<<<dim3(DIM/32,    DIM/32),    256>>>(Wq, wqh, wql, DIM,    DIM);
    wsplit_kernel<<<dim3(DIM/32,    DIM/32),    256>>>(Wk, wkh, wkl, DIM,    DIM);
    wsplit_kernel<<<dim3(DIM/32,    DIM/32),    256>>>(Wv, wvh, wvl, DIM,    DIM);
    wsplit_kernel<<<dim3(DIM/32,    DIM/32),    256>>>(Wo, woh, wol, DIM,    DIM);
    wsplit_kernel<<<dim3(HIDDEN/32, DIM/32),    256>>>(W1, w1h, w1l, DIM,    HIDDEN);
    wsplit_kernel<<<dim3(DIM/32,    HIDDEN/32), 256>>>(W2, w2h, w2l, HIDDEN, DIM);

    // h = LN1(x), split
    ln_kernel<<<TOK, 256>>>(x, g1, b1, hhi, hlo);
    // q,k = h@W + b -> bf16 hi/lo [b,h,t,d]; v -> bf16 hi/lo [b,h,d,t]
    gemm_mma<EPI_NONE, 1, false><<<dim3(DIM/BN, TOK/BM), 256, SM_GEMM>>>(
        hhi, hlo, wqh, wql, bq, nullptr, nullptr, qhi, qlo, TOK, DIM, DIM);
    gemm_mma<EPI_NONE, 1, false><<<dim3(DIM/BN, TOK/BM), 256, SM_GEMM>>>(
        hhi, hlo, wkh, wkl, bk, nullptr, nullptr, khi, klo, TOK, DIM, DIM);
    gemm_mma<EPI_NONE, 2, false><<<dim3(DIM/BN, TOK/BM), 256, SM_GEMM>>>(
        hhi, hlo, wvh, wvl, bv, nullptr, nullptr, vthi, vtlo, TOK, DIM, DIM);
    // o = softmax(qk^T/8) v -> bf16 hi/lo [b,t,C]
    attn_mma<<<dim3(SEQ/128, BATCH*HEADS), 256, SM_ATTN>>>(
        qhi, qlo, khi, klo, vthi, vtlo, ohi, olo);
    // x1 = x + o@Wo + bo  (f32)
    gemm_mma<EPI_RES, 0, false><<<dim3(DIM/BN, TOK/BM), 256, SM_GEMM>>>(
        ohi, olo, woh, wol, bo, x, x1, nullptr, nullptr, TOK, DIM, DIM);
    // h2 = LN2(x1), split
    ln_kernel<<<TOK, 256>>>(x1, g2, b2, h2hi, h2lo);
    // a = gelu(h2@W1 + bf1), split bf16
    gemm_mma<EPI_GELU, 0, true ><<<dim3(HIDDEN/BN, TOK/BM), 256, SM_GEMM>>>(
        h2hi, h2lo, w1h, w1l, bf1, nullptr, nullptr, ahi, alo, TOK, HIDDEN, DIM);
    // out = x1 + a@W2 + bf2  (f32)
    gemm_mma<EPI_RES, 0, false><<<dim3(DIM/BN, TOK/BM), 256, SM_GEMM>>>(
        ahi, alo, w2h, w2l, bf2, x1, out, nullptr, nullptr, TOK, DIM, HIDDEN);
}